// round 4
// baseline (speedup 1.0000x reference)
#include <cuda_runtime.h>
#include <cuda_bf16.h>
#include <math.h>

// Problem constants
#define Bb 256
#define Ss 1024
#define Dd 64
#define HD 128           // H*D
#define NJ 40            // hidden units
#define TILE 64          // rows per tile in main kernel
#define NTILES (Ss / TILE)

// Scratch (static device allocations are allowed)
__device__ float g_ytrans[Bb * HD];                 // normalized y transform
__device__ float g_weff[2L * Bb * Dd * (2 * NJ)];   // [br][b][d][h*40+j]  ~10.5 MB
__device__ float g_cvec[2L * Bb * (2 * NJ)];        // [br][b][h*40+j]

// ---------------------------------------------------------------------------
// P1: y_trans = l2norm(prelu(y @ w_ty + b_ty))   [B,128]
// ---------------------------------------------------------------------------
__global__ void p1_kernel(const float* __restrict__ y,
                          const float* __restrict__ wty,
                          const float* __restrict__ bty,
                          const float* __restrict__ atyp) {
    int b = blockIdx.x;
    int c = threadIdx.x;          // 0..127
    __shared__ float sy[64];
    __shared__ float sred[4];
    if (c < 64) sy[c] = y[b * 64 + c];
    __syncthreads();
    float acc = bty[c];
#pragma unroll
    for (int d = 0; d < 64; d++) acc += sy[d] * wty[d * 128 + c];
    float a = *atyp;
    float v = (acc >= 0.f) ? acc : a * acc;
    float ss = v * v;
#pragma unroll
    for (int off = 16; off > 0; off >>= 1) ss += __shfl_xor_sync(0xffffffffu, ss, off);
    if ((c & 31) == 0) sred[c >> 5] = ss;
    __syncthreads();
    float tot = sred[0] + sred[1] + sred[2] + sred[3];
    g_ytrans[b * 128 + c] = v / fmaxf(sqrtf(tot), 1e-12f);
}

// ---------------------------------------------------------------------------
// P2: per (branch,b): W_eff [64][80] and c [80]
// ---------------------------------------------------------------------------
__global__ void p2_kernel(const float* __restrict__ w1,
                          const float* __restrict__ b1,
                          const float* __restrict__ uid,
                          const float* __restrict__ osb,
                          const float* __restrict__ zipc,
                          int br) {
    __shared__ float syt[128];
    __shared__ float sside[56];
    int b = blockIdx.x;
    int t = threadIdx.x;
    if (t < 128) syt[t] = g_ytrans[b * 128 + t];
    if (t < 32) sside[t] = uid[b * 32 + t];
    else if (t < 40) sside[t] = osb[b * 8 + (t - 32)];
    else if (t < 56) sside[t] = zipc[b * 16 + (t - 40)];
    __syncthreads();

    size_t wbase = ((size_t)(br * Bb + b)) * (Dd * 2 * NJ);
    for (int i = t; i < Dd * 2 * NJ; i += blockDim.x) {
        int d = i / (2 * NJ);
        int hj = i - d * (2 * NJ);
        int h = hj / NJ;
        int j = hj - h * NJ;
        g_weff[wbase + i] = w1[d * NJ + j] + w1[(128 + d) * NJ + j]
                          + syt[h * 64 + d] * w1[(64 + d) * NJ + j];
    }
    if (t < 2 * NJ) {
        int h = t / NJ, j = t - h * NJ;
        float acc = b1[j];
#pragma unroll 4
        for (int d = 0; d < 64; d++)
            acc += syt[h * 64 + d] * (w1[(192 + d) * NJ + j] - w1[(128 + d) * NJ + j]);
#pragma unroll 4
        for (int k = 0; k < 56; k++)
            acc += sside[k] * w1[(256 + k) * NJ + j];
        g_cvec[(size_t)(br * Bb + b) * (2 * NJ) + t] = acc;
    }
}

// ---------------------------------------------------------------------------
// Main fused kernel: one block per (b). 256 threads.
//  stage1: t = prelu(x@W + b), l2norm over 128  (64-row tiles)
//  stage2: p[h] = prelu(xh@W_eff + c) @ w2 + b2
//  accum : out[h][:] += xh_h * p[h]
// ---------------------------------------------------------------------------
// smem layout (floats):
#define OFF_W    0                      // 64*128   = 8192
#define OFF_WE   8192                   // 64*80    = 5120
#define OFF_BX   13312                  // 128
#define OFF_C    13440                  // 80
#define OFF_W2   13520                  // 40
#define OFF_P    13560                  // 64*2     = 128
#define OFF_ACC  13688                  // 2*128    = 256
#define OFF_X    13952                  // 64*64    = 4096 (16B aligned)
#define OFF_T    18048                  // 64*132   = 8448 (padded stride)
#define SMEM_FLOATS 26496
#define SMEM_BYTES (SMEM_FLOATS * 4)
#define TSTRIDE 132

__global__ void __launch_bounds__(256, 2)
main_kernel(const float* __restrict__ x,      // [B,S,64] for this branch
            const float* __restrict__ wX,     // [64,128]
            const float* __restrict__ bX,     // [128]
            const float* __restrict__ aXp,    // scalar
            const float* __restrict__ a1p,    // scalar
            const float* __restrict__ b2p,    // scalar
            const float* __restrict__ w2,     // [40]
            int br,
            float* __restrict__ out)          // [B,128] for this branch
{
    extern __shared__ float sm[];
    float* sW   = sm + OFF_W;
    float* sWe  = sm + OFF_WE;
    float* sbx  = sm + OFF_BX;
    float* sc   = sm + OFF_C;
    float* sw2  = sm + OFF_W2;
    float* sp   = sm + OFF_P;
    float* sacc = sm + OFF_ACC;
    float* sx   = sm + OFF_X;
    float* st   = sm + OFF_T;

    const int tid  = threadIdx.x;
    const int b    = blockIdx.x;
    const int lane = tid & 31;
    const int wrp  = tid >> 5;

    // --- stage-in of per-block constants ---
    {
        const float4* wsrc = (const float4*)wX;
        for (int i = tid; i < 2048; i += 256) ((float4*)sW)[i] = wsrc[i];
        size_t wbase = ((size_t)(br * Bb + b)) * (Dd * 2 * NJ);
        const float4* wesrc = (const float4*)(g_weff + wbase);
        for (int i = tid; i < 1280; i += 256) ((float4*)sWe)[i] = wesrc[i];
        if (tid < 128) sbx[tid] = bX[tid];
        if (tid < 80)  sc[tid]  = g_cvec[(size_t)(br * Bb + b) * 80 + tid];
        if (tid < 40)  sw2[tid] = w2[tid];
        sacc[tid] = 0.f;
    }
    const float aXv = *aXp;
    const float a1v = *a1p;
    const float b2v = *b2p;
    __syncthreads();

    const float* xb = x + (size_t)b * Ss * Dd;

    for (int tile = 0; tile < NTILES; tile++) {
        // ---- load x tile [64][64] (contiguous, coalesced) ----
        {
            const float4* src = (const float4*)(xb + (size_t)tile * TILE * Dd);
            for (int i = tid; i < 1024; i += 256) ((float4*)sx)[i] = src[i];
        }
        __syncthreads();

        // ---- stage1: t = prelu(x@W + b); l2norm; write st (normalized) ----
        {
            const int r0 = wrp * 8;        // 8 rows per warp
            const int c0 = lane * 4;       // 4 cols per lane
            float acc[8][4];
            float4 bv = *(const float4*)&sbx[c0];
#pragma unroll
            for (int i = 0; i < 8; i++) {
                acc[i][0] = bv.x; acc[i][1] = bv.y; acc[i][2] = bv.z; acc[i][3] = bv.w;
            }
#pragma unroll 8
            for (int d = 0; d < 64; d++) {
                float4 wv = *(const float4*)&sW[d * 128 + c0];
#pragma unroll
                for (int i = 0; i < 8; i++) {
                    float xv = sx[(r0 + i) * 64 + d];
                    acc[i][0] += xv * wv.x;
                    acc[i][1] += xv * wv.y;
                    acc[i][2] += xv * wv.z;
                    acc[i][3] += xv * wv.w;
                }
            }
#pragma unroll
            for (int i = 0; i < 8; i++) {
#pragma unroll
                for (int j = 0; j < 4; j++) {
                    float v = acc[i][j];
                    acc[i][j] = (v >= 0.f) ? v : aXv * v;
                }
                float ss = acc[i][0] * acc[i][0] + acc[i][1] * acc[i][1]
                         + acc[i][2] * acc[i][2] + acc[i][3] * acc[i][3];
#pragma unroll
                for (int off = 16; off > 0; off >>= 1)
                    ss += __shfl_xor_sync(0xffffffffu, ss, off);
                float rn = 1.0f / fmaxf(sqrtf(ss), 1e-12f);
                float4 sv;
                sv.x = acc[i][0] * rn; sv.y = acc[i][1] * rn;
                sv.z = acc[i][2] * rn; sv.w = acc[i][3] * rn;
                *(float4*)&st[(r0 + i) * TSTRIDE + c0] = sv;
            }
        }
        __syncthreads();

        // ---- stage2: p[r][h] = prelu(xh@We + c) . w2 + b2 ----
        {
            const int jj = tid & 7;        // unit lane (covers j = jj+8k)
            const int rs = tid >> 3;       // 0..31
            const int rA = rs;             // rows rA and rA+32
            const int rB = rs + 32;
            float a0A[5], a1A[5], a0B[5], a1B[5];
#pragma unroll
            for (int k = 0; k < 5; k++) {
                float c0v = sc[jj + 8 * k];
                float c1v = sc[40 + jj + 8 * k];
                a0A[k] = c0v; a0B[k] = c0v;
                a1A[k] = c1v; a1B[k] = c1v;
            }
#pragma unroll 4
            for (int d = 0; d < 64; d++) {
                float xA0 = st[rA * TSTRIDE + d];
                float xA1 = st[rA * TSTRIDE + 64 + d];
                float xB0 = st[rB * TSTRIDE + d];
                float xB1 = st[rB * TSTRIDE + 64 + d];
#pragma unroll
                for (int k = 0; k < 5; k++) {
                    float w0 = sWe[d * 80 + jj + 8 * k];
                    float w1v = sWe[d * 80 + 40 + jj + 8 * k];
                    a0A[k] += xA0 * w0;
                    a1A[k] += xA1 * w1v;
                    a0B[k] += xB0 * w0;
                    a1B[k] += xB1 * w1v;
                }
            }
            float pA0 = 0.f, pA1 = 0.f, pB0 = 0.f, pB1 = 0.f;
#pragma unroll
            for (int k = 0; k < 5; k++) {
                float wv = sw2[jj + 8 * k];
                float h;
                h = a0A[k]; h = (h >= 0.f) ? h : a1v * h; pA0 += h * wv;
                h = a1A[k]; h = (h >= 0.f) ? h : a1v * h; pA1 += h * wv;
                h = a0B[k]; h = (h >= 0.f) ? h : a1v * h; pB0 += h * wv;
                h = a1B[k]; h = (h >= 0.f) ? h : a1v * h; pB1 += h * wv;
            }
#pragma unroll
            for (int off = 1; off < 8; off <<= 1) {
                pA0 += __shfl_xor_sync(0xffffffffu, pA0, off);
                pA1 += __shfl_xor_sync(0xffffffffu, pA1, off);
                pB0 += __shfl_xor_sync(0xffffffffu, pB0, off);
                pB1 += __shfl_xor_sync(0xffffffffu, pB1, off);
            }
            if (jj == 0) {
                sp[rA * 2 + 0] = pA0 + b2v;
                sp[rA * 2 + 1] = pA1 + b2v;
                sp[rB * 2 + 0] = pB0 + b2v;
                sp[rB * 2 + 1] = pB1 + b2v;
            }
        }
        __syncthreads();

        // ---- accumulate out[h][c] += xh * p ----
        {
            int c = tid & 127;
            int half = tid >> 7;           // rows [half*32, half*32+32)
            int h = c >> 6;
            float local = 0.f;
            int rb = half * 32;
#pragma unroll 8
            for (int r = rb; r < rb + 32; r++)
                local += st[r * TSTRIDE + c] * sp[r * 2 + h];
            sacc[half * 128 + c] += local;
        }
        __syncthreads();
    }

    if (tid < 128) out[(size_t)b * 128 + tid] = sacc[tid] + sacc[128 + tid];
}

// ---------------------------------------------------------------------------
extern "C" void kernel_launch(void* const* d_in, const int* in_sizes, int n_in,
                              void* d_out, int out_size) {
    const float* lx   = (const float*)d_in[0];
    const float* nx   = (const float*)d_in[1];
    const float* y    = (const float*)d_in[2];
    const float* uid  = (const float*)d_in[3];
    const float* osb  = (const float*)d_in[4];
    const float* zipc = (const float*)d_in[5];
    const float* wty  = (const float*)d_in[6];
    const float* bty  = (const float*)d_in[7];
    const float* aty  = (const float*)d_in[8];
    const float* wlx  = (const float*)d_in[9];
    const float* blx  = (const float*)d_in[10];
    const float* alx  = (const float*)d_in[11];
    const float* wnx  = (const float*)d_in[12];
    const float* bnx  = (const float*)d_in[13];
    const float* anx  = (const float*)d_in[14];
    const float* lw1  = (const float*)d_in[15];
    const float* lb1  = (const float*)d_in[16];
    const float* la1  = (const float*)d_in[17];
    const float* lw2  = (const float*)d_in[18];
    const float* lb2  = (const float*)d_in[19];
    const float* nw1  = (const float*)d_in[20];
    const float* nb1  = (const float*)d_in[21];
    const float* na1  = (const float*)d_in[22];
    const float* nw2  = (const float*)d_in[23];
    const float* nb2  = (const float*)d_in[24];

    float* out = (float*)d_out;

    cudaFuncSetAttribute(main_kernel, cudaFuncAttributeMaxDynamicSharedMemorySize, SMEM_BYTES);

    p1_kernel<<<Bb, 128>>>(y, wty, bty, aty);
    p2_kernel<<<Bb, 256>>>(lw1, lb1, uid, osb, zipc, 0);
    p2_kernel<<<Bb, 256>>>(nw1, nb1, uid, osb, zipc, 1);
    main_kernel<<<Bb, 256, SMEM_BYTES>>>(lx, wlx, blx, alx, la1, lb2, lw2, 0, out);
    main_kernel<<<Bb, 256, SMEM_BYTES>>>(nx, wnx, bnx, anx, na1, nb2, nw2, 1, out + Bb * HD);
}

// round 5
// speedup vs baseline: 1.0335x; 1.0335x over previous
#include <cuda_runtime.h>
#include <cuda_bf16.h>
#include <math.h>

#define Bb 256
#define Ss 1024
#define Dd 64
#define HD 128
#define NJ 40
#define TILE 64
#define NTILES (Ss / TILE)
#define WESTRIDE 96          // padded per-d stride of repacked W_eff

typedef unsigned long long ull;

__device__ __forceinline__ ull dup2(float x) {
    ull r; asm("mov.b64 %0, {%1, %1};" : "=l"(r) : "f"(x)); return r;
}
__device__ __forceinline__ void fma2(ull& d, ull a, ull b) {
    asm("fma.rn.f32x2 %0, %1, %2, %3;" : "=l"(d) : "l"(a), "l"(b), "l"(d));
}
__device__ __forceinline__ void unpk(float& lo, float& hi, ull v) {
    asm("mov.b64 {%0, %1}, %2;" : "=f"(lo), "=f"(hi) : "l"(v));
}

// Scratch
__device__ float g_weff[2L * Bb * Dd * WESTRIDE];   // repacked: [br][b][d][jj*12 + slot]
__device__ float g_cvec[2L * Bb * WESTRIDE];        // [br][b][jj*12 + slot]

// slot -> (h,k):  0-3: h0 k0-3 | 4-7: h1 k0-3 | 8: h0 k4 | 9: h1 k4 | 10,11: pad
__device__ __forceinline__ bool slot_map(int s, int& h, int& k) {
    if (s < 4)       { h = 0; k = s;     return true; }
    else if (s < 8)  { h = 1; k = s - 4; return true; }
    else if (s == 8) { h = 0; k = 4;     return true; }
    else if (s == 9) { h = 1; k = 4;     return true; }
    return false;
}

// ---------------------------------------------------------------------------
// Prep: per (b, branch) compute y_trans locally, then W_eff (repacked) and c.
// ---------------------------------------------------------------------------
__global__ void prep_kernel(const float* __restrict__ y,
                            const float* __restrict__ wty,
                            const float* __restrict__ bty,
                            const float* __restrict__ atyp,
                            const float* __restrict__ uid,
                            const float* __restrict__ osb,
                            const float* __restrict__ zipc,
                            const float* __restrict__ lw1,
                            const float* __restrict__ lb1,
                            const float* __restrict__ nw1,
                            const float* __restrict__ nb1) {
    __shared__ float sy[64];
    __shared__ float syt[128];
    __shared__ float sside[56];
    __shared__ float sred[4];
    int b = blockIdx.x;
    int br = blockIdx.y;
    int t = threadIdx.x;
    const float* w1 = br ? nw1 : lw1;
    const float* b1 = br ? nb1 : lb1;

    if (t < 64) sy[t] = y[b * 64 + t];
    if (t >= 64 && t < 96) sside[t - 64] = uid[b * 32 + (t - 64)];
    else if (t >= 96 && t < 104) sside[32 + (t - 96)] = osb[b * 8 + (t - 96)];
    else if (t >= 104 && t < 120) sside[40 + (t - 104)] = zipc[b * 16 + (t - 104)];
    __syncthreads();

    float vv = 0.f;
    if (t < 128) {
        float acc = bty[t];
#pragma unroll 8
        for (int d = 0; d < 64; d++) acc += sy[d] * wty[d * 128 + t];
        float a = *atyp;
        vv = (acc >= 0.f) ? acc : a * acc;
        float ss = vv * vv;
#pragma unroll
        for (int off = 16; off > 0; off >>= 1) ss += __shfl_xor_sync(0xffffffffu, ss, off);
        if ((t & 31) == 0) sred[t >> 5] = ss;
    }
    __syncthreads();
    if (t < 128) {
        float tot = sred[0] + sred[1] + sred[2] + sred[3];
        syt[t] = vv / fmaxf(sqrtf(tot), 1e-12f);
    }
    __syncthreads();

    // W_eff repacked
    size_t wbase = ((size_t)(br * Bb + b)) * (Dd * WESTRIDE);
    for (int i = t; i < Dd * WESTRIDE; i += blockDim.x) {
        int d = i / WESTRIDE;
        int q = i - d * WESTRIDE;
        int jj = q / 12;
        int s = q - jj * 12;
        int h, k;
        float v = 0.f;
        if (slot_map(s, h, k)) {
            int j = jj + 8 * k;
            v = w1[d * NJ + j] + w1[(128 + d) * NJ + j]
              + syt[h * 64 + d] * w1[(64 + d) * NJ + j];
        }
        g_weff[wbase + i] = v;
    }
    // c repacked
    if (t < WESTRIDE) {
        int jj = t / 12;
        int s = t - jj * 12;
        int h, k;
        float v = 0.f;
        if (slot_map(s, h, k)) {
            int j = jj + 8 * k;
            float acc = b1[j];
#pragma unroll 4
            for (int d = 0; d < 64; d++)
                acc += syt[h * 64 + d] * (w1[(192 + d) * NJ + j] - w1[(128 + d) * NJ + j]);
#pragma unroll 4
            for (int k2 = 0; k2 < 56; k2++)
                acc += sside[k2] * w1[(256 + k2) * NJ + j];
            v = acc;
        }
        g_cvec[(size_t)(br * Bb + b) * WESTRIDE + t] = v;
    }
}

// ---------------------------------------------------------------------------
// Main fused kernel: grid (256, 2); block 256.
// ---------------------------------------------------------------------------
// smem layout (floats)
#define OFF_W    0                       // 64*128 = 8192
#define OFF_WE   8192                    // 64*96  = 6144
#define OFF_X    14336                   // 64*64  = 4096
#define OFF_T    18432                   // 64*132 = 8448
#define OFF_BX   26880                   // 128
#define OFF_C    27008                   // 96
#define OFF_P    27104                   // 128
#define OFF_ACC  27232                   // 256
#define SMEM_FLOATS 27488
#define SMEM_BYTES (SMEM_FLOATS * 4)
#define TSTRIDE 132

__global__ void __launch_bounds__(256, 2)
main_kernel(const float* __restrict__ lx,
            const float* __restrict__ nx,
            const float* __restrict__ wlx, const float* __restrict__ blx,
            const float* __restrict__ alx,
            const float* __restrict__ wnx, const float* __restrict__ bnx,
            const float* __restrict__ anx,
            const float* __restrict__ la1, const float* __restrict__ lb2,
            const float* __restrict__ lw2,
            const float* __restrict__ na1, const float* __restrict__ nb2,
            const float* __restrict__ nw2,
            float* __restrict__ out)
{
    extern __shared__ float sm[];
    float* sW   = sm + OFF_W;
    float* sWe  = sm + OFF_WE;
    float* sx   = sm + OFF_X;
    float* st   = sm + OFF_T;
    float* sbx  = sm + OFF_BX;
    float* sc   = sm + OFF_C;
    float* sp   = sm + OFF_P;
    float* sacc = sm + OFF_ACC;

    const int tid  = threadIdx.x;
    const int b    = blockIdx.x;
    const int br   = blockIdx.y;
    const int lane = tid & 31;
    const int wrp  = tid >> 5;

    const float* x   = br ? nx  : lx;
    const float* wX  = br ? wnx : wlx;
    const float* bX  = br ? bnx : blx;
    const float aXv  = br ? *anx : *alx;
    const float a1v  = br ? *na1 : *la1;
    const float b2v  = br ? *nb2 : *lb2;
    const float* w2  = br ? nw2 : lw2;

    // ---- stage-in constants ----
    {
        const float4* wsrc = (const float4*)wX;
        for (int i = tid; i < 2048; i += 256) ((float4*)sW)[i] = wsrc[i];
        size_t wbase = ((size_t)(br * Bb + b)) * (Dd * WESTRIDE);
        const float4* wesrc = (const float4*)(g_weff + wbase);
        for (int i = tid; i < (Dd * WESTRIDE) / 4; i += 256) ((float4*)sWe)[i] = wesrc[i];
        if (tid < 128) sbx[tid] = bX[tid];
        if (tid < WESTRIDE) sc[tid] = g_cvec[(size_t)(br * Bb + b) * WESTRIDE + tid];
        sacc[tid] = 0.f;
    }
    __syncthreads();

    // stage1 thread geometry
    const int r0 = wrp * 8;
    const int c0 = lane * 4;
    // stage2 thread geometry
    const int jj = tid & 7;
    const int rs = tid >> 3;     // 0..31
    const int rA = rs;
    const int rB = rs + 32;

    // stage2 per-thread constants (registers, hoisted out of tile loop)
    ull cP[4]; float cS[2]; float w2v[5];
    {
        const float* cr = &sc[jj * 12];
        ulonglong2 c01 = *(const ulonglong2*)cr;       // (h0k0,h0k1),(h0k2,h0k3)
        ulonglong2 c23 = *(const ulonglong2*)(cr + 4); // (h1k0,h1k1),(h1k2,h1k3)
        float2 c4 = *(const float2*)(cr + 8);          // h0k4, h1k4
        cP[0] = c01.x; cP[1] = c01.y; cP[2] = c23.x; cP[3] = c23.y;
        cS[0] = c4.x; cS[1] = c4.y;
#pragma unroll
        for (int k = 0; k < 5; k++) w2v[k] = w2[jj + 8 * k];
    }
    ulonglong2 bq = *(const ulonglong2*)&sbx[c0];

    const float* xb = x + (size_t)b * Ss * Dd;

    for (int tile = 0; tile < NTILES; tile++) {
        // ---- load x tile [64][64] ----
        {
            const float4* src = (const float4*)(xb + (size_t)tile * TILE * Dd);
            for (int i = tid; i < 1024; i += 256) ((float4*)sx)[i] = src[i];
        }
        __syncthreads();

        // ---- stage1: t = l2norm(prelu(x@W + b)) via packed f32x2 ----
        {
            ull acc[8][2];
#pragma unroll
            for (int i = 0; i < 8; i++) { acc[i][0] = bq.x; acc[i][1] = bq.y; }

#pragma unroll 4
            for (int d4 = 0; d4 < 64; d4 += 4) {
                float4 xv[8];
#pragma unroll
                for (int i = 0; i < 8; i++)
                    xv[i] = *(const float4*)&sx[(r0 + i) * 64 + d4];
#pragma unroll
                for (int dd = 0; dd < 4; dd++) {
                    ulonglong2 wv = *(const ulonglong2*)&sW[(d4 + dd) * 128 + c0];
#pragma unroll
                    for (int i = 0; i < 8; i++) {
                        float xs = (dd == 0) ? xv[i].x : (dd == 1) ? xv[i].y
                                 : (dd == 2) ? xv[i].z : xv[i].w;
                        ull xd = dup2(xs);
                        fma2(acc[i][0], xd, wv.x);
                        fma2(acc[i][1], xd, wv.y);
                    }
                }
            }
#pragma unroll
            for (int i = 0; i < 8; i++) {
                float v0, v1, v2, v3;
                unpk(v0, v1, acc[i][0]);
                unpk(v2, v3, acc[i][1]);
                v0 = (v0 >= 0.f) ? v0 : aXv * v0;
                v1 = (v1 >= 0.f) ? v1 : aXv * v1;
                v2 = (v2 >= 0.f) ? v2 : aXv * v2;
                v3 = (v3 >= 0.f) ? v3 : aXv * v3;
                float ss = v0 * v0 + v1 * v1 + v2 * v2 + v3 * v3;
#pragma unroll
                for (int off = 16; off > 0; off >>= 1)
                    ss += __shfl_xor_sync(0xffffffffu, ss, off);
                float rn = 1.0f / fmaxf(sqrtf(ss), 1e-12f);
                float4 sv;
                sv.x = v0 * rn; sv.y = v1 * rn; sv.z = v2 * rn; sv.w = v3 * rn;
                *(float4*)&st[(r0 + i) * TSTRIDE + c0] = sv;
            }
        }
        __syncthreads();

        // ---- stage2: p = prelu(xh @ W_eff + c) . w2 + b2 (packed over k) ----
        {
            ull aPA[4], aPB[4];
            float aSA[2], aSB[2];
#pragma unroll
            for (int m = 0; m < 4; m++) { aPA[m] = cP[m]; aPB[m] = cP[m]; }
            aSA[0] = cS[0]; aSA[1] = cS[1]; aSB[0] = cS[0]; aSB[1] = cS[1];

#pragma unroll 4
            for (int d4 = 0; d4 < 64; d4 += 4) {
                float4 xA0 = *(const float4*)&st[rA * TSTRIDE + d4];
                float4 xA1 = *(const float4*)&st[rA * TSTRIDE + 64 + d4];
                float4 xB0 = *(const float4*)&st[rB * TSTRIDE + d4];
                float4 xB1 = *(const float4*)&st[rB * TSTRIDE + 64 + d4];
#pragma unroll
                for (int dd = 0; dd < 4; dd++) {
                    const float* wr = &sWe[(d4 + dd) * WESTRIDE + jj * 12];
                    ulonglong2 w01 = *(const ulonglong2*)wr;
                    ulonglong2 w23 = *(const ulonglong2*)(wr + 4);
                    float2 w4 = *(const float2*)(wr + 8);
                    float fA0 = (dd == 0) ? xA0.x : (dd == 1) ? xA0.y : (dd == 2) ? xA0.z : xA0.w;
                    float fA1 = (dd == 0) ? xA1.x : (dd == 1) ? xA1.y : (dd == 2) ? xA1.z : xA1.w;
                    float fB0 = (dd == 0) ? xB0.x : (dd == 1) ? xB0.y : (dd == 2) ? xB0.z : xB0.w;
                    float fB1 = (dd == 0) ? xB1.x : (dd == 1) ? xB1.y : (dd == 2) ? xB1.z : xB1.w;
                    ull xA0d = dup2(fA0), xA1d = dup2(fA1);
                    ull xB0d = dup2(fB0), xB1d = dup2(fB1);
                    fma2(aPA[0], xA0d, w01.x); fma2(aPA[1], xA0d, w01.y);
                    fma2(aPA[2], xA1d, w23.x); fma2(aPA[3], xA1d, w23.y);
                    aSA[0] = fmaf(fA0, w4.x, aSA[0]);
                    aSA[1] = fmaf(fA1, w4.y, aSA[1]);
                    fma2(aPB[0], xB0d, w01.x); fma2(aPB[1], xB0d, w01.y);
                    fma2(aPB[2], xB1d, w23.x); fma2(aPB[3], xB1d, w23.y);
                    aSB[0] = fmaf(fB0, w4.x, aSB[0]);
                    aSB[1] = fmaf(fB1, w4.y, aSB[1]);
                }
            }
            // epilogue: prelu + dot(w2)
            float pA0, pA1, pB0, pB1;
            {
                float h0, h1, h2, h3, h4, s;
                // A, head0
                unpk(h0, h1, aPA[0]); unpk(h2, h3, aPA[1]); h4 = aSA[0];
                h0 = (h0 >= 0.f) ? h0 : a1v * h0; h1 = (h1 >= 0.f) ? h1 : a1v * h1;
                h2 = (h2 >= 0.f) ? h2 : a1v * h2; h3 = (h3 >= 0.f) ? h3 : a1v * h3;
                h4 = (h4 >= 0.f) ? h4 : a1v * h4;
                s = h0 * w2v[0] + h1 * w2v[1] + h2 * w2v[2] + h3 * w2v[3] + h4 * w2v[4];
                pA0 = s;
                // A, head1
                unpk(h0, h1, aPA[2]); unpk(h2, h3, aPA[3]); h4 = aSA[1];
                h0 = (h0 >= 0.f) ? h0 : a1v * h0; h1 = (h1 >= 0.f) ? h1 : a1v * h1;
                h2 = (h2 >= 0.f) ? h2 : a1v * h2; h3 = (h3 >= 0.f) ? h3 : a1v * h3;
                h4 = (h4 >= 0.f) ? h4 : a1v * h4;
                s = h0 * w2v[0] + h1 * w2v[1] + h2 * w2v[2] + h3 * w2v[3] + h4 * w2v[4];
                pA1 = s;
                // B, head0
                unpk(h0, h1, aPB[0]); unpk(h2, h3, aPB[1]); h4 = aSB[0];
                h0 = (h0 >= 0.f) ? h0 : a1v * h0; h1 = (h1 >= 0.f) ? h1 : a1v * h1;
                h2 = (h2 >= 0.f) ? h2 : a1v * h2; h3 = (h3 >= 0.f) ? h3 : a1v * h3;
                h4 = (h4 >= 0.f) ? h4 : a1v * h4;
                s = h0 * w2v[0] + h1 * w2v[1] + h2 * w2v[2] + h3 * w2v[3] + h4 * w2v[4];
                pB0 = s;
                // B, head1
                unpk(h0, h1, aPB[2]); unpk(h2, h3, aPB[3]); h4 = aSB[1];
                h0 = (h0 >= 0.f) ? h0 : a1v * h0; h1 = (h1 >= 0.f) ? h1 : a1v * h1;
                h2 = (h2 >= 0.f) ? h2 : a1v * h2; h3 = (h3 >= 0.f) ? h3 : a1v * h3;
                h4 = (h4 >= 0.f) ? h4 : a1v * h4;
                s = h0 * w2v[0] + h1 * w2v[1] + h2 * w2v[2] + h3 * w2v[3] + h4 * w2v[4];
                pB1 = s;
            }
#pragma unroll
            for (int off = 1; off < 8; off <<= 1) {
                pA0 += __shfl_xor_sync(0xffffffffu, pA0, off);
                pA1 += __shfl_xor_sync(0xffffffffu, pA1, off);
                pB0 += __shfl_xor_sync(0xffffffffu, pB0, off);
                pB1 += __shfl_xor_sync(0xffffffffu, pB1, off);
            }
            if (jj == 0) {
                sp[rA * 2 + 0] = pA0 + b2v;
                sp[rA * 2 + 1] = pA1 + b2v;
                sp[rB * 2 + 0] = pB0 + b2v;
                sp[rB * 2 + 1] = pB1 + b2v;
            }
        }
        __syncthreads();

        // ---- stage3: out[h][c] += xh * p ----
        {
            int c = tid & 127;
            int half = tid >> 7;
            int h = c >> 6;
            float local = 0.f;
            int rb = half * 32;
#pragma unroll 8
            for (int r = rb; r < rb + 32; r++)
                local += st[r * TSTRIDE + c] * sp[r * 2 + h];
            sacc[half * 128 + c] += local;
        }
        __syncthreads();
    }

    if (tid < 128)
        out[(size_t)br * Bb * HD + (size_t)b * HD + tid] = sacc[tid] + sacc[128 + tid];
}

// ---------------------------------------------------------------------------
extern "C" void kernel_launch(void* const* d_in, const int* in_sizes, int n_in,
                              void* d_out, int out_size) {
    const float* lx   = (const float*)d_in[0];
    const float* nx   = (const float*)d_in[1];
    const float* y    = (const float*)d_in[2];
    const float* uid  = (const float*)d_in[3];
    const float* osb  = (const float*)d_in[4];
    const float* zipc = (const float*)d_in[5];
    const float* wty  = (const float*)d_in[6];
    const float* bty  = (const float*)d_in[7];
    const float* aty  = (const float*)d_in[8];
    const float* wlx  = (const float*)d_in[9];
    const float* blx  = (const float*)d_in[10];
    const float* alx  = (const float*)d_in[11];
    const float* wnx  = (const float*)d_in[12];
    const float* bnx  = (const float*)d_in[13];
    const float* anx  = (const float*)d_in[14];
    const float* lw1  = (const float*)d_in[15];
    const float* lb1  = (const float*)d_in[16];
    const float* la1  = (const float*)d_in[17];
    const float* lw2  = (const float*)d_in[18];
    const float* lb2  = (const float*)d_in[19];
    const float* nw1  = (const float*)d_in[20];
    const float* nb1  = (const float*)d_in[21];
    const float* na1  = (const float*)d_in[22];
    const float* nw2  = (const float*)d_in[23];
    const float* nb2  = (const float*)d_in[24];

    float* out = (float*)d_out;

    cudaFuncSetAttribute(main_kernel, cudaFuncAttributeMaxDynamicSharedMemorySize, SMEM_BYTES);

    dim3 g2(Bb, 2);
    prep_kernel<<<g2, 256>>>(y, wty, bty, aty, uid, osb, zipc, lw1, lb1, nw1, nb1);
    main_kernel<<<g2, 256, SMEM_BYTES>>>(lx, nx, wlx, blx, alx, wnx, bnx, anx,
                                         la1, lb2, lw2, na1, nb2, nw2, out);
}

// round 12
// speedup vs baseline: 1.3646x; 1.3203x over previous
#include <cuda_runtime.h>
#include <cuda_bf16.h>
#include <math.h>
#include <stdint.h>

#define Bb 256
#define Ss 1024
#define Dd 64
#define HD 128
#define NJ 40
#define TILE 64
#define NTILES (Ss / TILE)
#define WESTRIDE 96
#define TSTRIDE 132

// padded bf16 row strides (in bf16 elems); byte strides 144 / 272 (16B multiples)
#define XSTR 72
#define WSTR 136

typedef unsigned long long ull;

// ---------------- f32x2 helpers (stage2 scalar path) ----------------
__device__ __forceinline__ ull dup2(float x) {
    ull r; asm("mov.b64 %0, {%1, %1};" : "=l"(r) : "f"(x)); return r;
}
__device__ __forceinline__ void fma2(ull& d, ull a, ull b) {
    asm("fma.rn.f32x2 %0, %1, %2, %3;" : "=l"(d) : "l"(a), "l"(b), "l"(d));
}
__device__ __forceinline__ void unpk(float& lo, float& hi, ull v) {
    asm("mov.b64 {%0, %1}, %2;" : "=f"(lo), "=f"(hi) : "l"(v));
}

// ---------------- tensor-core helpers (portable: ldmatrix + mma.sync) -------
__device__ __forceinline__ uint32_t smem_u32(const void* p) {
    uint32_t a;
    asm("{ .reg .u64 t; cvta.to.shared.u64 t, %1; cvt.u32.u64 %0, t; }" : "=r"(a) : "l"(p));
    return a;
}
__device__ __forceinline__ void ldsm4(uint32_t* r, uint32_t addr) {
    asm volatile("ldmatrix.sync.aligned.m8n8.x4.shared.b16 {%0,%1,%2,%3}, [%4];"
        : "=r"(r[0]), "=r"(r[1]), "=r"(r[2]), "=r"(r[3]) : "r"(addr));
}
__device__ __forceinline__ void ldsm4t(uint32_t* r, uint32_t addr) {
    asm volatile("ldmatrix.sync.aligned.m8n8.x4.trans.shared.b16 {%0,%1,%2,%3}, [%4];"
        : "=r"(r[0]), "=r"(r[1]), "=r"(r[2]), "=r"(r[3]) : "r"(addr));
}
__device__ __forceinline__ void mma_bf16(float* c, const uint32_t* a,
                                         uint32_t b0, uint32_t b1) {
    asm volatile("mma.sync.aligned.m16n8k16.row.col.f32.bf16.bf16.f32 "
        "{%0,%1,%2,%3}, {%4,%5,%6,%7}, {%8,%9}, {%0,%1,%2,%3};"
        : "+f"(c[0]), "+f"(c[1]), "+f"(c[2]), "+f"(c[3])
        : "r"(a[0]), "r"(a[1]), "r"(a[2]), "r"(a[3]), "r"(b0), "r"(b1));
}

// ---------------- scratch ----------------
__device__ float g_weff[2L * Bb * Dd * WESTRIDE];
__device__ float g_cvec[2L * Bb * WESTRIDE];
__device__ __nv_bfloat16 g_wh[2 * Dd * 128];    // W hi, row-major [d][n]
__device__ __nv_bfloat16 g_wl[2 * Dd * 128];    // W lo

__device__ __forceinline__ bool slot_map(int s, int& h, int& k) {
    if (s < 4)       { h = 0; k = s;     return true; }
    else if (s < 8)  { h = 1; k = s - 4; return true; }
    else if (s == 8) { h = 0; k = 4;     return true; }
    else if (s == 9) { h = 1; k = 4;     return true; }
    return false;
}

// ---------------------------------------------------------------------------
// Prep: y_trans -> W_eff (repacked), c ; also W bf16 hi/lo (b==0 blocks)
// ---------------------------------------------------------------------------
__global__ void prep_kernel(const float* __restrict__ y,
                            const float* __restrict__ wty,
                            const float* __restrict__ bty,
                            const float* __restrict__ atyp,
                            const float* __restrict__ uid,
                            const float* __restrict__ osb,
                            const float* __restrict__ zipc,
                            const float* __restrict__ lw1,
                            const float* __restrict__ lb1,
                            const float* __restrict__ nw1,
                            const float* __restrict__ nb1,
                            const float* __restrict__ wlx,
                            const float* __restrict__ wnx) {
    __shared__ float sy[64];
    __shared__ float syt[128];
    __shared__ float sside[56];
    __shared__ float sred[4];
    int b = blockIdx.x;
    int br = blockIdx.y;
    int t = threadIdx.x;
    const float* w1 = br ? nw1 : lw1;
    const float* b1 = br ? nb1 : lb1;

    if (t < 64) sy[t] = y[b * 64 + t];
    if (t >= 64 && t < 96) sside[t - 64] = uid[b * 32 + (t - 64)];
    else if (t >= 96 && t < 104) sside[32 + (t - 96)] = osb[b * 8 + (t - 96)];
    else if (t >= 104 && t < 120) sside[40 + (t - 104)] = zipc[b * 16 + (t - 104)];
    __syncthreads();

    float vv = 0.f;
    if (t < 128) {
        float acc = bty[t];
#pragma unroll 8
        for (int d = 0; d < 64; d++) acc += sy[d] * wty[d * 128 + t];
        float a = *atyp;
        vv = (acc >= 0.f) ? acc : a * acc;
        float ss = vv * vv;
#pragma unroll
        for (int off = 16; off > 0; off >>= 1) ss += __shfl_xor_sync(0xffffffffu, ss, off);
        if ((t & 31) == 0) sred[t >> 5] = ss;
    }
    __syncthreads();
    if (t < 128) {
        float tot = sred[0] + sred[1] + sred[2] + sred[3];
        syt[t] = vv / fmaxf(sqrtf(tot), 1e-12f);
    }
    __syncthreads();

    size_t wbase = ((size_t)(br * Bb + b)) * (Dd * WESTRIDE);
    for (int i = t; i < Dd * WESTRIDE; i += blockDim.x) {
        int d = i / WESTRIDE;
        int q = i - d * WESTRIDE;
        int jj = q / 12;
        int s = q - jj * 12;
        int h, k;
        float v = 0.f;
        if (slot_map(s, h, k)) {
            int j = jj + 8 * k;
            v = w1[d * NJ + j] + w1[(128 + d) * NJ + j]
              + syt[h * 64 + d] * w1[(64 + d) * NJ + j];
        }
        g_weff[wbase + i] = v;
    }
    if (t < WESTRIDE) {
        int jj = t / 12;
        int s = t - jj * 12;
        int h, k;
        float v = 0.f;
        if (slot_map(s, h, k)) {
            int j = jj + 8 * k;
            float acc = b1[j];
#pragma unroll 4
            for (int d = 0; d < 64; d++)
                acc += syt[h * 64 + d] * (w1[(192 + d) * NJ + j] - w1[(128 + d) * NJ + j]);
#pragma unroll 4
            for (int k2 = 0; k2 < 56; k2++)
                acc += sside[k2] * w1[(256 + k2) * NJ + j];
            v = acc;
        }
        g_cvec[(size_t)(br * Bb + b) * WESTRIDE + t] = v;
    }

    // W bf16 hi/lo, row-major [d][n] (once per branch)
    if (b == 0) {
        const float* wX = br ? wnx : wlx;
        for (int i = t; i < Dd * 128; i += blockDim.x) {
            float v = wX[i];
            __nv_bfloat16 hi = __float2bfloat16(v);
            __nv_bfloat16 lo = __float2bfloat16(v - __bfloat162float(hi));
            g_wh[br * Dd * 128 + i] = hi;
            g_wl[br * Dd * 128 + i] = lo;
        }
    }
}

// ---------------------------------------------------------------------------
// Main kernel: grid (256, 2), block 256.
//   stage1 via mma.sync bf16 (hi/lo split), stage2/3 scalar f32x2.
// ---------------------------------------------------------------------------
// smem byte offsets
#define OFF_XH   0          // 64*144 = 9216 (x hi, padded)   } union with ST
#define OFF_XL   9216       // 9216   (x lo)                  }
#define OFF_ST   0          // 64*132*4 = 33792 fp32
#define OFF_WH   33792      // 64*272 = 17408 (W hi, padded)
#define OFF_WL   51200      // 17408
#define OFF_WE   68608      // 24576
#define OFF_BX   93184      // 512
#define OFF_RN   93696      // 256
#define OFF_SRED 93952      // 512
#define OFF_SP   94464      // 512
#define OFF_SACC 94976      // 1024
#define OFF_SC   96000      // 384
#define SMEM_BYTES 96384

__global__ void __launch_bounds__(256, 2)
main_kernel(const float* __restrict__ lx,
            const float* __restrict__ nx,
            const float* __restrict__ blx, const float* __restrict__ alx,
            const float* __restrict__ bnx, const float* __restrict__ anx,
            const float* __restrict__ la1, const float* __restrict__ lb2,
            const float* __restrict__ lw2,
            const float* __restrict__ na1, const float* __restrict__ nb2,
            const float* __restrict__ nw2,
            float* __restrict__ out)
{
    extern __shared__ char smc[];
    float* st   = (float*)(smc + OFF_ST);
    float* sWe  = (float*)(smc + OFF_WE);
    float* sbx  = (float*)(smc + OFF_BX);
    float* srn  = (float*)(smc + OFF_RN);
    float* sred = (float*)(smc + OFF_SRED);
    float* sp   = (float*)(smc + OFF_SP);
    float* sacc = (float*)(smc + OFF_SACC);
    float* sc   = (float*)(smc + OFF_SC);

    const int tid  = threadIdx.x;
    const int b    = blockIdx.x;
    const int br   = blockIdx.y;
    const int lane = tid & 31;
    const int wrp  = tid >> 5;

    const float* x  = br ? nx  : lx;
    const float* bX = br ? bnx : blx;
    const float aXv = br ? *anx : *alx;
    const float a1v = br ? *na1 : *la1;
    const float b2v = br ? *nb2 : *lb2;
    const float* w2 = br ? nw2 : lw2;

    const uint32_t sb = smem_u32(smc);

    // ---- stage-in constants ----
    {
        size_t wbase = ((size_t)(br * Bb + b)) * (Dd * WESTRIDE);
        const float4* wesrc = (const float4*)(g_weff + wbase);
        for (int i = tid; i < (Dd * WESTRIDE) / 4; i += 256) ((float4*)sWe)[i] = wesrc[i];
        if (tid < 128) sbx[tid] = bX[tid];
        if (tid < WESTRIDE) sc[tid] = g_cvec[(size_t)(br * Bb + b) * WESTRIDE + tid];
        sacc[tid] = 0.f;
        // W hi/lo into padded smem, 4 bf16 (8B) chunks
        const ull* gh = (const ull*)(g_wh + br * Dd * 128);
        const ull* gl = (const ull*)(g_wl + br * Dd * 128);
#pragma unroll
        for (int k = 0; k < 8; k++) {
            int q = tid + k * 256;               // 0..2047
            int row = q >> 5;                    // d
            int c8 = (q & 31) * 8;               // byte offset of 4 bf16
            *(ull*)(smc + OFF_WH + row * (WSTR * 2) + c8) = gh[q];
            *(ull*)(smc + OFF_WL + row * (WSTR * 2) + c8) = gl[q];
        }
    }
    __syncthreads();

    // stage1 MMA geometry: 8 warps = 4 m-blocks x 2 n-halves
    const int mb = wrp & 3;          // 16-row block
    const int nh = wrp >> 2;         // 64-col half
    // ldmatrix lane-address bases
    const int lm = lane >> 3;        // matrix index 0..3
    const int lr = lane & 7;
    // A: row = mb*16 + (lm&1)*8 + lr ; kbyte = (lm>>1)*16 (+32 per kstep)
    const uint32_t aoff = (uint32_t)((mb * 16 + (lm & 1) * 8 + lr) * (XSTR * 2) + (lm >> 1) * 16);
    // B: krow = (lm&1)*8 + lr ; ncolbyte = (nh*64 + (lm>>1)*8)*2 (+32 per g, +16*WSTR*2 per kstep)
    const uint32_t boff = (uint32_t)(((lm & 1) * 8 + lr) * (WSTR * 2) + (nh * 64 + (lm >> 1) * 8) * 2);

    // stage2 per-thread constants
    const int jj = tid & 7;
    const int rs = tid >> 3;
    const int rA = rs & 31;
    const int rB = rA + 32;
    ull cP[4]; float cS[2]; float w2v[5];
    {
        const float* cr = &sc[jj * 12];
        ulonglong2 c01 = *(const ulonglong2*)cr;
        ulonglong2 c23 = *(const ulonglong2*)(cr + 4);
        float2 c4 = *(const float2*)(cr + 8);
        cP[0] = c01.x; cP[1] = c01.y; cP[2] = c23.x; cP[3] = c23.y;
        cS[0] = c4.x; cS[1] = c4.y;
#pragma unroll
        for (int k = 0; k < 5; k++) w2v[k] = w2[jj + 8 * k];
    }

    const float* xb = x + (size_t)b * Ss * Dd;
    const int r0 = mb * 16 + (lane >> 2);    // epilogue row (and r0+8)

    for (int tile = 0; tile < NTILES; tile++) {
        // ---- convert x tile [64x64] fp32 -> bf16 hi/lo (padded rows) ----
        {
            const float4* src = (const float4*)(xb + (size_t)tile * TILE * Dd);
#pragma unroll
            for (int k = 0; k < 4; k++) {
                int q = tid + k * 256;           // 0..1023 float4s
                float4 v = src[q];
                int row = q >> 4;
                int c8 = (q & 15) * 8;
                __nv_bfloat16 h0 = __float2bfloat16(v.x);
                __nv_bfloat16 h1 = __float2bfloat16(v.y);
                __nv_bfloat16 h2 = __float2bfloat16(v.z);
                __nv_bfloat16 h3 = __float2bfloat16(v.w);
                __nv_bfloat16 l0 = __float2bfloat16(v.x - __bfloat162float(h0));
                __nv_bfloat16 l1 = __float2bfloat16(v.y - __bfloat162float(h1));
                __nv_bfloat16 l2 = __float2bfloat16(v.z - __bfloat162float(h2));
                __nv_bfloat16 l3 = __float2bfloat16(v.w - __bfloat162float(h3));
                ull ph = (ull)__bfloat16_as_ushort(h0)
                       | ((ull)__bfloat16_as_ushort(h1) << 16)
                       | ((ull)__bfloat16_as_ushort(h2) << 32)
                       | ((ull)__bfloat16_as_ushort(h3) << 48);
                ull pl = (ull)__bfloat16_as_ushort(l0)
                       | ((ull)__bfloat16_as_ushort(l1) << 16)
                       | ((ull)__bfloat16_as_ushort(l2) << 32)
                       | ((ull)__bfloat16_as_ushort(l3) << 48);
                *(ull*)(smc + OFF_XH + row * (XSTR * 2) + c8) = ph;
                *(ull*)(smc + OFF_XL + row * (XSTR * 2) + c8) = pl;
            }
        }
        __syncthreads();

        // ---- stage1 MMA: C = xhi@Whi + xlo@Whi + xhi@Wlo ----
        float C[8][4];
#pragma unroll
        for (int j = 0; j < 8; j++) { C[j][0] = C[j][1] = C[j][2] = C[j][3] = 0.f; }
#pragma unroll
        for (int ks = 0; ks < 4; ks++) {
            uint32_t ah[4], al[4];
            ldsm4(ah, sb + OFF_XH + aoff + ks * 32);
            ldsm4(al, sb + OFF_XL + aoff + ks * 32);
#pragma unroll
            for (int g = 0; g < 4; g++) {
                uint32_t bh[4], bl[4];
                uint32_t bstep = boff + (uint32_t)(ks * 16 * (WSTR * 2) + g * 32);
                ldsm4t(bh, sb + OFF_WH + bstep);
                ldsm4t(bl, sb + OFF_WL + bstep);
                mma_bf16(C[2 * g],     ah, bh[0], bh[1]);
                mma_bf16(C[2 * g],     al, bh[0], bh[1]);
                mma_bf16(C[2 * g],     ah, bl[0], bl[1]);
                mma_bf16(C[2 * g + 1], ah, bh[2], bh[3]);
                mma_bf16(C[2 * g + 1], al, bh[2], bh[3]);
                mma_bf16(C[2 * g + 1], ah, bl[2], bl[3]);
            }
        }

        // ---- epilogue: bias + prelu + row ssq ----
        {
            float ssq0 = 0.f, ssq1 = 0.f;
#pragma unroll
            for (int j = 0; j < 8; j++) {
                int col = nh * 64 + j * 8 + (lane & 3) * 2;
                float2 bb = *(const float2*)&sbx[col];
                float v0 = C[j][0] + bb.x; v0 = (v0 >= 0.f) ? v0 : aXv * v0;
                float v1 = C[j][1] + bb.y; v1 = (v1 >= 0.f) ? v1 : aXv * v1;
                float v2 = C[j][2] + bb.x; v2 = (v2 >= 0.f) ? v2 : aXv * v2;
                float v3 = C[j][3] + bb.y; v3 = (v3 >= 0.f) ? v3 : aXv * v3;
                C[j][0] = v0; C[j][1] = v1; C[j][2] = v2; C[j][3] = v3;
                ssq0 += v0 * v0 + v1 * v1;
                ssq1 += v2 * v2 + v3 * v3;
            }
            ssq0 += __shfl_xor_sync(0xffffffffu, ssq0, 1);
            ssq0 += __shfl_xor_sync(0xffffffffu, ssq0, 2);
            ssq1 += __shfl_xor_sync(0xffffffffu, ssq1, 1);
            ssq1 += __shfl_xor_sync(0xffffffffu, ssq1, 2);
            if ((lane & 3) == 0) {
                sred[r0 * 2 + nh] = ssq0;
                sred[(r0 + 8) * 2 + nh] = ssq1;
            }
        }
        __syncthreads();
        if (tid < 64)
            srn[tid] = 1.0f / fmaxf(sqrtf(sred[tid * 2] + sred[tid * 2 + 1]), 1e-12f);
        __syncthreads();

        // ---- normalize from regs -> st (overwrites xhi/xlo union; safe: all
        //      warps finished ldmatrix reads before the sreds sync above) ----
        {
            float rn0 = srn[r0], rn1 = srn[r0 + 8];
#pragma unroll
            for (int j = 0; j < 8; j++) {
                int col = nh * 64 + j * 8 + (lane & 3) * 2;
                float2 o0; o0.x = C[j][0] * rn0; o0.y = C[j][1] * rn0;
                float2 o1; o1.x = C[j][2] * rn1; o1.y = C[j][3] * rn1;
                *(float2*)&st[r0 * TSTRIDE + col] = o0;
                *(float2*)&st[(r0 + 8) * TSTRIDE + col] = o1;
            }
        }
        __syncthreads();

        // ---- stage2: p = prelu(xh @ W_eff + c) . w2 + b2 (f32x2 packed) ----
        {
            ull aPA[4], aPB[4];
            float aSA[2], aSB[2];
#pragma unroll
            for (int m = 0; m < 4; m++) { aPA[m] = cP[m]; aPB[m] = cP[m]; }
            aSA[0] = cS[0]; aSA[1] = cS[1]; aSB[0] = cS[0]; aSB[1] = cS[1];

#pragma unroll 4
            for (int d4 = 0; d4 < 64; d4 += 4) {
                float4 xA0 = *(const float4*)&st[rA * TSTRIDE + d4];
                float4 xA1 = *(const float4*)&st[rA * TSTRIDE + 64 + d4];
                float4 xB0 = *(const float4*)&st[rB * TSTRIDE + d4];
                float4 xB1 = *(const float4*)&st[rB * TSTRIDE + 64 + d4];
#pragma unroll
                for (int dd = 0; dd < 4; dd++) {
                    const float* wr = &sWe[(d4 + dd) * WESTRIDE + jj * 12];
                    ulonglong2 w01 = *(const ulonglong2*)wr;
                    ulonglong2 w23 = *(const ulonglong2*)(wr + 4);
                    float2 w4 = *(const float2*)(wr + 8);
                    float fA0 = (dd == 0) ? xA0.x : (dd == 1) ? xA0.y : (dd == 2) ? xA0.z : xA0.w;
                    float fA1 = (dd == 0) ? xA1.x : (dd == 1) ? xA1.y : (dd == 2) ? xA1.z : xA1.w;
                    float fB0 = (dd == 0) ? xB0.x : (dd == 1) ? xB0.y : (dd == 2) ? xB0.z : xB0.w;
                    float fB1 = (dd == 0) ? xB1.x : (dd == 1) ? xB1.y : (dd == 2) ? xB1.z : xB1.w;
                    ull xA0d = dup2(fA0), xA1d = dup2(fA1);
                    ull xB0d = dup2(fB0), xB1d = dup2(fB1);
                    fma2(aPA[0], xA0d, w01.x); fma2(aPA[1], xA0d, w01.y);
                    fma2(aPA[2], xA1d, w23.x); fma2(aPA[3], xA1d, w23.y);
                    aSA[0] = fmaf(fA0, w4.x, aSA[0]);
                    aSA[1] = fmaf(fA1, w4.y, aSA[1]);
                    fma2(aPB[0], xB0d, w01.x); fma2(aPB[1], xB0d, w01.y);
                    fma2(aPB[2], xB1d, w23.x); fma2(aPB[3], xB1d, w23.y);
                    aSB[0] = fmaf(fB0, w4.x, aSB[0]);
                    aSB[1] = fmaf(fB1, w4.y, aSB[1]);
                }
            }
            float pA0, pA1, pB0, pB1;
            {
                float h0, h1, h2, h3, h4, s;
                unpk(h0, h1, aPA[0]); unpk(h2, h3, aPA[1]); h4 = aSA[0];
                h0 = (h0 >= 0.f) ? h0 : a1v * h0; h1 = (h1 >= 0.f) ? h1 : a1v * h1;
                h2 = (h2 >= 0.f) ? h2 : a1v * h2; h3 = (h3 >= 0.f) ? h3 : a1v * h3;
                h4 = (h4 >= 0.f) ? h4 : a1v * h4;
                s = h0 * w2v[0] + h1 * w2v[1] + h2 * w2v[2] + h3 * w2v[3] + h4 * w2v[4];
                pA0 = s;
                unpk(h0, h1, aPA[2]); unpk(h2, h3, aPA[3]); h4 = aSA[1];
                h0 = (h0 >= 0.f) ? h0 : a1v * h0; h1 = (h1 >= 0.f) ? h1 : a1v * h1;
                h2 = (h2 >= 0.f) ? h2 : a1v * h2; h3 = (h3 >= 0.f) ? h3 : a1v * h3;
                h4 = (h4 >= 0.f) ? h4 : a1v * h4;
                s = h0 * w2v[0] + h1 * w2v[1] + h2 * w2v[2] + h3 * w2v[3] + h4 * w2v[4];
                pA1 = s;
                unpk(h0, h1, aPB[0]); unpk(h2, h3, aPB[1]); h4 = aSB[0];
                h0 = (h0 >= 0.f) ? h0 : a1v * h0; h1 = (h1 >= 0.f) ? h1 : a1v * h1;
                h2 = (h2 >= 0.f) ? h2 : a1v * h2; h3 = (h3 >= 0.f) ? h3 : a1v * h3;
                h4 = (h4 >= 0.f) ? h4 : a1v * h4;
                s = h0 * w2v[0] + h1 * w2v[1] + h2 * w2v[2] + h3 * w2v[3] + h4 * w2v[4];
                pB0 = s;
                unpk(h0, h1, aPB[2]); unpk(h2, h3, aPB[3]); h4 = aSB[1];
                h0 = (h0 >= 0.f) ? h0 : a1v * h0; h1 = (h1 >= 0.f) ? h1 : a1v * h1;
                h2 = (h2 >= 0.f) ? h2 : a1v * h2; h3 = (h3 >= 0.f) ? h3 : a1v * h3;
                h4 = (h4 >= 0.f) ? h4 : a1v * h4;
                s = h0 * w2v[0] + h1 * w2v[1] + h2 * w2v[2] + h3 * w2v[3] + h4 * w2v[4];
                pB1 = s;
            }
#pragma unroll
            for (int off = 1; off < 8; off <<= 1) {
                pA0 += __shfl_xor_sync(0xffffffffu, pA0, off);
                pA1 += __shfl_xor_sync(0xffffffffu, pA1, off);
                pB0 += __shfl_xor_sync(0xffffffffu, pB0, off);
                pB1 += __shfl_xor_sync(0xffffffffu, pB1, off);
            }
            if (jj == 0) {
                sp[rA * 2 + 0] = pA0 + b2v;
                sp[rA * 2 + 1] = pA1 + b2v;
                sp[rB * 2 + 0] = pB0 + b2v;
                sp[rB * 2 + 1] = pB1 + b2v;
            }
        }
        __syncthreads();

        // ---- stage3: out[h][c] += xh * p ----
        {
            int c = tid & 127;
            int rhalf = tid >> 7;
            int h = c >> 6;
            float local = 0.f;
            int rb0 = rhalf * 32;
#pragma unroll 8
            for (int r = rb0; r < rb0 + 32; r++)
                local += st[r * TSTRIDE + c] * sp[r * 2 + h];
            sacc[rhalf * 128 + c] += local;
        }
        __syncthreads();
    }

    if (tid < 128)
        out[(size_t)br * Bb * HD + (size_t)b * HD + tid] = sacc[tid] + sacc[128 + tid];
}

// ---------------------------------------------------------------------------
extern "C" void kernel_launch(void* const* d_in, const int* in_sizes, int n_in,
                              void* d_out, int out_size) {
    const float* lx   = (const float*)d_in[0];
    const float* nx   = (const float*)d_in[1];
    const float* y    = (const float*)d_in[2];
    const float* uid  = (const float*)d_in[3];
    const float* osb  = (const float*)d_in[4];
    const float* zipc = (const float*)d_in[5];
    const float* wty  = (const float*)d_in[6];
    const float* bty  = (const float*)d_in[7];
    const float* aty  = (const float*)d_in[8];
    const float* wlx  = (const float*)d_in[9];
    const float* blx  = (const float*)d_in[10];
    const float* alx  = (const float*)d_in[11];
    const float* wnx  = (const float*)d_in[12];
    const float* bnx  = (const float*)d_in[13];
    const float* anx  = (const float*)d_in[14];
    const float* lw1  = (const float*)d_in[15];
    const float* lb1  = (const float*)d_in[16];
    const float* la1  = (const float*)d_in[17];
    const float* lw2  = (const float*)d_in[18];
    const float* lb2  = (const float*)d_in[19];
    const float* nw1  = (const float*)d_in[20];
    const float* nb1  = (const float*)d_in[21];
    const float* na1  = (const float*)d_in[22];
    const float* nw2  = (const float*)d_in[23];
    const float* nb2  = (const float*)d_in[24];

    float* out = (float*)d_out;

    cudaFuncSetAttribute(main_kernel, cudaFuncAttributeMaxDynamicSharedMemorySize, SMEM_BYTES);

    dim3 g2(Bb, 2);
    prep_kernel<<<g2, 256>>>(y, wty, bty, aty, uid, osb, zipc,
                             lw1, lb1, nw1, nb1, wlx, wnx);
    main_kernel<<<g2, 256, SMEM_BYTES>>>(lx, nx, blx, alx, bnx, anx,
                                         la1, lb2, lw2, na1, nb2, nw2, out);
}

// round 13
// speedup vs baseline: 2.4095x; 1.7657x over previous
#include <cuda_runtime.h>
#include <cuda_bf16.h>
#include <math.h>
#include <stdint.h>

#define Bb 256
#define Ss 1024
#define Dd 64
#define HD 128
#define NJ 40
#define TILE 64
#define NTILES (Ss / TILE)

// bf16 row strides (elements): x tiles 72 (144B), st 136 (272B), W 136 (272B), We 104 (208B)
#define XSTR 72
#define STSTR 136
#define WSTR 136
#define WESTR 104

typedef unsigned long long ull;

// ---------------- tensor-core helpers ----------------
__device__ __forceinline__ uint32_t smem_u32(const void* p) {
    uint32_t a;
    asm("{ .reg .u64 t; cvta.to.shared.u64 t, %1; cvt.u32.u64 %0, t; }" : "=r"(a) : "l"(p));
    return a;
}
__device__ __forceinline__ void ldsm4(uint32_t* r, uint32_t addr) {
    asm volatile("ldmatrix.sync.aligned.m8n8.x4.shared.b16 {%0,%1,%2,%3}, [%4];"
        : "=r"(r[0]), "=r"(r[1]), "=r"(r[2]), "=r"(r[3]) : "r"(addr));
}
__device__ __forceinline__ void ldsm4t(uint32_t* r, uint32_t addr) {
    asm volatile("ldmatrix.sync.aligned.m8n8.x4.trans.shared.b16 {%0,%1,%2,%3}, [%4];"
        : "=r"(r[0]), "=r"(r[1]), "=r"(r[2]), "=r"(r[3]) : "r"(addr));
}
__device__ __forceinline__ void mma_bf16(float* c, const uint32_t* a,
                                         uint32_t b0, uint32_t b1) {
    asm volatile("mma.sync.aligned.m16n8k16.row.col.f32.bf16.bf16.f32 "
        "{%0,%1,%2,%3}, {%4,%5,%6,%7}, {%8,%9}, {%0,%1,%2,%3};"
        : "+f"(c[0]), "+f"(c[1]), "+f"(c[2]), "+f"(c[3])
        : "r"(a[0]), "r"(a[1]), "r"(a[2]), "r"(a[3]), "r"(b0), "r"(b1));
}

// ---------------- scratch ----------------
__device__ __nv_bfloat16 g_wh[2 * Dd * 128];          // x-transform W hi [d][n]
__device__ __nv_bfloat16 g_wl[2 * Dd * 128];          // lo
__device__ __nv_bfloat16 g_weH[2L * Bb * 64 * 96];    // W_eff hi [br][b][d][96] (2 heads x 48, pad zero)
__device__ __nv_bfloat16 g_weL[2L * Bb * 64 * 96];    // lo
__device__ float g_cvec2[2L * Bb * 80];               // c bias [br][b][h*40+j]

// ---------------------------------------------------------------------------
// Prep: y_trans -> W_eff bf16 hi/lo + c ; x-transform W bf16 hi/lo (b==0)
// ---------------------------------------------------------------------------
__global__ void prep_kernel(const float* __restrict__ y,
                            const float* __restrict__ wty,
                            const float* __restrict__ bty,
                            const float* __restrict__ atyp,
                            const float* __restrict__ uid,
                            const float* __restrict__ osb,
                            const float* __restrict__ zipc,
                            const float* __restrict__ lw1,
                            const float* __restrict__ lb1,
                            const float* __restrict__ nw1,
                            const float* __restrict__ nb1,
                            const float* __restrict__ wlx,
                            const float* __restrict__ wnx) {
    __shared__ float sy[64];
    __shared__ float syt[128];
    __shared__ float sside[56];
    __shared__ float sred[4];
    int b = blockIdx.x;
    int br = blockIdx.y;
    int t = threadIdx.x;
    const float* w1 = br ? nw1 : lw1;
    const float* b1 = br ? nb1 : lb1;

    if (t < 64) sy[t] = y[b * 64 + t];
    if (t >= 64 && t < 96) sside[t - 64] = uid[b * 32 + (t - 64)];
    else if (t >= 96 && t < 104) sside[32 + (t - 96)] = osb[b * 8 + (t - 96)];
    else if (t >= 104 && t < 120) sside[40 + (t - 104)] = zipc[b * 16 + (t - 104)];
    __syncthreads();

    float vv = 0.f;
    if (t < 128) {
        float acc = bty[t];
#pragma unroll 8
        for (int d = 0; d < 64; d++) acc += sy[d] * wty[d * 128 + t];
        float a = *atyp;
        vv = (acc >= 0.f) ? acc : a * acc;
        float ss = vv * vv;
#pragma unroll
        for (int off = 16; off > 0; off >>= 1) ss += __shfl_xor_sync(0xffffffffu, ss, off);
        if ((t & 31) == 0) sred[t >> 5] = ss;
    }
    __syncthreads();
    if (t < 128) {
        float tot = sred[0] + sred[1] + sred[2] + sred[3];
        syt[t] = vv / fmaxf(sqrtf(tot), 1e-12f);
    }
    __syncthreads();

    // W_eff bf16 hi/lo: [d][col], col = h*48 + jj (jj<40 real, else 0)
    size_t base = ((size_t)(br * Bb + b)) * (64 * 96);
    for (int i = t; i < 64 * 96; i += blockDim.x) {
        int d = i / 96;
        int col = i - d * 96;
        int h = col / 48;
        int jj = col - h * 48;
        float v = 0.f;
        if (jj < 40) {
            v = w1[d * NJ + jj] + w1[(128 + d) * NJ + jj]
              + syt[h * 64 + d] * w1[(64 + d) * NJ + jj];
        }
        __nv_bfloat16 hi = __float2bfloat16(v);
        g_weH[base + i] = hi;
        g_weL[base + i] = __float2bfloat16(v - __bfloat162float(hi));
    }
    // c bias, plain layout [h*40+j]
    if (t < 80) {
        int h = t / 40, j = t - h * 40;
        float acc = b1[j];
#pragma unroll 4
        for (int d = 0; d < 64; d++)
            acc += syt[h * 64 + d] * (w1[(192 + d) * NJ + j] - w1[(128 + d) * NJ + j]);
#pragma unroll 4
        for (int k2 = 0; k2 < 56; k2++)
            acc += sside[k2] * w1[(256 + k2) * NJ + j];
        g_cvec2[(size_t)(br * Bb + b) * 80 + t] = acc;
    }

    // x-transform W bf16 hi/lo (once per branch)
    if (b == 0) {
        const float* wX = br ? wnx : wlx;
        for (int i = t; i < Dd * 128; i += blockDim.x) {
            float v = wX[i];
            __nv_bfloat16 hi = __float2bfloat16(v);
            __nv_bfloat16 lo = __float2bfloat16(v - __bfloat162float(hi));
            g_wh[br * Dd * 128 + i] = hi;
            g_wl[br * Dd * 128 + i] = lo;
        }
    }
}

// ---------------------------------------------------------------------------
// Main kernel: grid (256, 2), block 256. Both stages on mma.sync bf16 hi/lo.
// ---------------------------------------------------------------------------
// smem byte offsets
#define OFF_XH   0          // 9216  (x hi)   } union with STH/STL
#define OFF_XL   9216       // 9216  (x lo)   }
#define OFF_STH  0          // 17408 (st hi, 64 x 272B)
#define OFF_STL  17408      // 17408 (st lo)
#define OFF_WH   34816      // 17408 (x-W hi)
#define OFF_WL   52224      // 17408
#define OFF_WEH  69632      // 13312 (W_eff hi, 64 x 208B)
#define OFF_WEL  82944      // 13312
#define OFF_BX   96256      // 512
#define OFF_SRN  96768      // 256
#define OFF_SRED 97024      // 512
#define OFF_SP   97536      // 512
#define OFF_SACC 98048      // 1024
#define OFF_CV   99072      // 320
#define OFF_W2   99392      // 160
#define SMEM_BYTES 99584

__global__ void __launch_bounds__(256, 2)
main_kernel(const float* __restrict__ lx,
            const float* __restrict__ nx,
            const float* __restrict__ blx, const float* __restrict__ alx,
            const float* __restrict__ bnx, const float* __restrict__ anx,
            const float* __restrict__ la1, const float* __restrict__ lb2,
            const float* __restrict__ lw2,
            const float* __restrict__ na1, const float* __restrict__ nb2,
            const float* __restrict__ nw2,
            float* __restrict__ out)
{
    extern __shared__ char smc[];
    float* sbx  = (float*)(smc + OFF_BX);
    float* srn  = (float*)(smc + OFF_SRN);
    float* sred = (float*)(smc + OFF_SRED);
    float* sp   = (float*)(smc + OFF_SP);
    float* sacc = (float*)(smc + OFF_SACC);
    float* scv  = (float*)(smc + OFF_CV);
    float* sw2  = (float*)(smc + OFF_W2);

    const int tid  = threadIdx.x;
    const int b    = blockIdx.x;
    const int br   = blockIdx.y;
    const int lane = tid & 31;
    const int wrp  = tid >> 5;

    const float* x  = br ? nx  : lx;
    const float* bX = br ? bnx : blx;
    const float aXv = br ? *anx : *alx;
    const float a1v = br ? *na1 : *la1;
    const float b2v = br ? *nb2 : *lb2;
    const float* w2 = br ? nw2 : lw2;

    const uint32_t sb = smem_u32(smc);

    // ---- stage-in constants ----
    {
        // x-transform W hi/lo into padded smem
        const ull* gh = (const ull*)(g_wh + br * Dd * 128);
        const ull* gl = (const ull*)(g_wl + br * Dd * 128);
#pragma unroll
        for (int k = 0; k < 8; k++) {
            int q = tid + k * 256;               // 0..2047
            int row = q >> 5;
            int c8 = (q & 31) * 8;
            *(ull*)(smc + OFF_WH + row * (WSTR * 2) + c8) = gh[q];
            *(ull*)(smc + OFF_WL + row * (WSTR * 2) + c8) = gl[q];
        }
        // W_eff hi/lo: global [d][96] -> smem stride 104 bf16 (u32 copy)
        size_t base = ((size_t)(br * Bb + b)) * (64 * 96);
        const uint32_t* geh = (const uint32_t*)(g_weH + base);
        const uint32_t* gel = (const uint32_t*)(g_weL + base);
        uint32_t* weh = (uint32_t*)(smc + OFF_WEH);
        uint32_t* wel = (uint32_t*)(smc + OFF_WEL);
        for (int i = tid; i < 64 * 48; i += 256) {
            int d = i / 48, q = i - d * 48;
            weh[d * 52 + q] = geh[i];
            wel[d * 52 + q] = gel[i];
        }
        if (tid < 128) sbx[tid] = bX[tid];
        if (tid < 80)  scv[tid] = g_cvec2[(size_t)(br * Bb + b) * 80 + tid];
        if (tid < 40)  sw2[tid] = w2[tid];
        sacc[tid] = 0.f;
    }
    __syncthreads();

    // stage1 MMA geometry: 8 warps = 4 m-blocks x 2 n-halves
    const int mb = wrp & 3;
    const int nh = wrp >> 2;
    const int lm = lane >> 3;
    const int lr = lane & 7;
    const uint32_t aoff = (uint32_t)((mb * 16 + (lm & 1) * 8 + lr) * (XSTR * 2) + (lm >> 1) * 16);
    const uint32_t boff = (uint32_t)(((lm & 1) * 8 + lr) * (WSTR * 2) + (nh * 64 + (lm >> 1) * 8) * 2);
    const int r0 = mb * 16 + (lane >> 2);

    // stage2 MMA geometry: 8 warps = 2 heads x 4 m-blocks
    const int head2 = wrp >> 2;
    const int mb2 = wrp & 3;
    const uint32_t a2off = (uint32_t)((mb2 * 16 + (lm & 1) * 8 + lr) * (STSTR * 2)
                                      + head2 * 128 + (lm >> 1) * 16);
    const uint32_t b2off = (uint32_t)(((lm & 1) * 8 + lr) * (WESTR * 2)
                                      + (head2 * 48 + (lm >> 1) * 8) * 2);
    // stage2 per-lane j constants
    float cb[5][2], w2l[5][2];
#pragma unroll
    for (int t5 = 0; t5 < 5; t5++) {
        int j0 = t5 * 8 + (lane & 3) * 2;
        cb[t5][0] = scv[head2 * 40 + j0];
        cb[t5][1] = scv[head2 * 40 + j0 + 1];
        w2l[t5][0] = sw2[j0];
        w2l[t5][1] = sw2[j0 + 1];
    }

    const float* xb = x + (size_t)b * Ss * Dd;

    for (int tile = 0; tile < NTILES; tile++) {
        // ---- convert x tile [64x64] fp32 -> bf16 hi/lo ----
        {
            const float4* src = (const float4*)(xb + (size_t)tile * TILE * Dd);
#pragma unroll
            for (int k = 0; k < 4; k++) {
                int q = tid + k * 256;
                float4 v = src[q];
                int row = q >> 4;
                int c8 = (q & 15) * 8;
                __nv_bfloat16 h0 = __float2bfloat16(v.x);
                __nv_bfloat16 h1 = __float2bfloat16(v.y);
                __nv_bfloat16 h2 = __float2bfloat16(v.z);
                __nv_bfloat16 h3 = __float2bfloat16(v.w);
                __nv_bfloat16 l0 = __float2bfloat16(v.x - __bfloat162float(h0));
                __nv_bfloat16 l1 = __float2bfloat16(v.y - __bfloat162float(h1));
                __nv_bfloat16 l2 = __float2bfloat16(v.z - __bfloat162float(h2));
                __nv_bfloat16 l3 = __float2bfloat16(v.w - __bfloat162float(h3));
                ull ph = (ull)__bfloat16_as_ushort(h0)
                       | ((ull)__bfloat16_as_ushort(h1) << 16)
                       | ((ull)__bfloat16_as_ushort(h2) << 32)
                       | ((ull)__bfloat16_as_ushort(h3) << 48);
                ull pl = (ull)__bfloat16_as_ushort(l0)
                       | ((ull)__bfloat16_as_ushort(l1) << 16)
                       | ((ull)__bfloat16_as_ushort(l2) << 32)
                       | ((ull)__bfloat16_as_ushort(l3) << 48);
                *(ull*)(smc + OFF_XH + row * (XSTR * 2) + c8) = ph;
                *(ull*)(smc + OFF_XL + row * (XSTR * 2) + c8) = pl;
            }
        }
        __syncthreads();

        // ---- stage1 MMA: C = xhi@Whi + xlo@Whi + xhi@Wlo ----
        float C[8][4];
#pragma unroll
        for (int j = 0; j < 8; j++) { C[j][0] = C[j][1] = C[j][2] = C[j][3] = 0.f; }
#pragma unroll
        for (int ks = 0; ks < 4; ks++) {
            uint32_t ah[4], al[4];
            ldsm4(ah, sb + OFF_XH + aoff + ks * 32);
            ldsm4(al, sb + OFF_XL + aoff + ks * 32);
#pragma unroll
            for (int g = 0; g < 4; g++) {
                uint32_t bh[4], bl[4];
                uint32_t bstep = boff + (uint32_t)(ks * 16 * (WSTR * 2) + g * 32);
                ldsm4t(bh, sb + OFF_WH + bstep);
                ldsm4t(bl, sb + OFF_WL + bstep);
                mma_bf16(C[2 * g],     ah, bh[0], bh[1]);
                mma_bf16(C[2 * g],     al, bh[0], bh[1]);
                mma_bf16(C[2 * g],     ah, bl[0], bl[1]);
                mma_bf16(C[2 * g + 1], ah, bh[2], bh[3]);
                mma_bf16(C[2 * g + 1], al, bh[2], bh[3]);
                mma_bf16(C[2 * g + 1], ah, bl[2], bl[3]);
            }
        }

        // ---- epilogue: bias + prelu + row ssq ----
        {
            float ssq0 = 0.f, ssq1 = 0.f;
#pragma unroll
            for (int j = 0; j < 8; j++) {
                int col = nh * 64 + j * 8 + (lane & 3) * 2;
                float2 bb = *(const float2*)&sbx[col];
                float v0 = C[j][0] + bb.x; v0 = (v0 >= 0.f) ? v0 : aXv * v0;
                float v1 = C[j][1] + bb.y; v1 = (v1 >= 0.f) ? v1 : aXv * v1;
                float v2 = C[j][2] + bb.x; v2 = (v2 >= 0.f) ? v2 : aXv * v2;
                float v3 = C[j][3] + bb.y; v3 = (v3 >= 0.f) ? v3 : aXv * v3;
                C[j][0] = v0; C[j][1] = v1; C[j][2] = v2; C[j][3] = v3;
                ssq0 += v0 * v0 + v1 * v1;
                ssq1 += v2 * v2 + v3 * v3;
            }
            ssq0 += __shfl_xor_sync(0xffffffffu, ssq0, 1);
            ssq0 += __shfl_xor_sync(0xffffffffu, ssq0, 2);
            ssq1 += __shfl_xor_sync(0xffffffffu, ssq1, 1);
            ssq1 += __shfl_xor_sync(0xffffffffu, ssq1, 2);
            if ((lane & 3) == 0) {
                sred[r0 * 2 + nh] = ssq0;
                sred[(r0 + 8) * 2 + nh] = ssq1;
            }
        }
        __syncthreads();    // all ldsm reads of XH/XL complete here
        if (tid < 64)
            srn[tid] = 1.0f / fmaxf(sqrtf(sred[tid * 2] + sred[tid * 2 + 1]), 1e-12f);
        __syncthreads();

        // ---- normalize from regs -> st bf16 hi/lo (overwrites XH/XL union) ----
        {
            float rn0 = srn[r0], rn1 = srn[r0 + 8];
#pragma unroll
            for (int j = 0; j < 8; j++) {
                int col = nh * 64 + j * 8 + (lane & 3) * 2;
                float v0 = C[j][0] * rn0, v1 = C[j][1] * rn0;
                float v2 = C[j][2] * rn1, v3 = C[j][3] * rn1;
                __nv_bfloat16 h0 = __float2bfloat16(v0), h1 = __float2bfloat16(v1);
                __nv_bfloat16 h2 = __float2bfloat16(v2), h3 = __float2bfloat16(v3);
                uint32_t ph0 = (uint32_t)__bfloat16_as_ushort(h0)
                             | ((uint32_t)__bfloat16_as_ushort(h1) << 16);
                uint32_t pl0 = (uint32_t)__bfloat16_as_ushort(__float2bfloat16(v0 - __bfloat162float(h0)))
                             | ((uint32_t)__bfloat16_as_ushort(__float2bfloat16(v1 - __bfloat162float(h1))) << 16);
                uint32_t ph1 = (uint32_t)__bfloat16_as_ushort(h2)
                             | ((uint32_t)__bfloat16_as_ushort(h3) << 16);
                uint32_t pl1 = (uint32_t)__bfloat16_as_ushort(__float2bfloat16(v2 - __bfloat162float(h2)))
                             | ((uint32_t)__bfloat16_as_ushort(__float2bfloat16(v3 - __bfloat162float(h3))) << 16);
                *(uint32_t*)(smc + OFF_STH + r0 * (STSTR * 2) + col * 2) = ph0;
                *(uint32_t*)(smc + OFF_STL + r0 * (STSTR * 2) + col * 2) = pl0;
                *(uint32_t*)(smc + OFF_STH + (r0 + 8) * (STSTR * 2) + col * 2) = ph1;
                *(uint32_t*)(smc + OFF_STL + (r0 + 8) * (STSTR * 2) + col * 2) = pl1;
            }
        }
        __syncthreads();

        // ---- stage2 MMA: C2 = st @ W_eff (hi/lo 3-product), then p = prelu(.)·w2 ----
        {
            float C2[5][4];
#pragma unroll
            for (int t5 = 0; t5 < 5; t5++)
                C2[t5][0] = C2[t5][1] = C2[t5][2] = C2[t5][3] = 0.f;
#pragma unroll
            for (int ks = 0; ks < 4; ks++) {
                uint32_t ah[4], al[4];
                ldsm4(ah, sb + OFF_STH + a2off + ks * 32);
                ldsm4(al, sb + OFF_STL + a2off + ks * 32);
#pragma unroll
                for (int ch = 0; ch < 3; ch++) {
                    uint32_t bh[4], bl[4];
                    uint32_t bstep = b2off + (uint32_t)(ks * 16 * (WESTR * 2) + ch * 32);
                    ldsm4t(bh, sb + OFF_WEH + bstep);
                    ldsm4t(bl, sb + OFF_WEL + bstep);
                    mma_bf16(C2[2 * ch], ah, bh[0], bh[1]);
                    mma_bf16(C2[2 * ch], al, bh[0], bh[1]);
                    mma_bf16(C2[2 * ch], ah, bl[0], bl[1]);
                    if (ch < 2) {
                        mma_bf16(C2[2 * ch + 1], ah, bh[2], bh[3]);
                        mma_bf16(C2[2 * ch + 1], al, bh[2], bh[3]);
                        mma_bf16(C2[2 * ch + 1], ah, bl[2], bl[3]);
                    }
                }
            }
            float ps0 = 0.f, ps1 = 0.f;
#pragma unroll
            for (int t5 = 0; t5 < 5; t5++) {
                float v;
                v = C2[t5][0] + cb[t5][0]; v = (v >= 0.f) ? v : a1v * v; ps0 += v * w2l[t5][0];
                v = C2[t5][1] + cb[t5][1]; v = (v >= 0.f) ? v : a1v * v; ps0 += v * w2l[t5][1];
                v = C2[t5][2] + cb[t5][0]; v = (v >= 0.f) ? v : a1v * v; ps1 += v * w2l[t5][0];
                v = C2[t5][3] + cb[t5][1]; v = (v >= 0.f) ? v : a1v * v; ps1 += v * w2l[t5][1];
            }
            ps0 += __shfl_xor_sync(0xffffffffu, ps0, 1);
            ps0 += __shfl_xor_sync(0xffffffffu, ps0, 2);
            ps1 += __shfl_xor_sync(0xffffffffu, ps1, 1);
            ps1 += __shfl_xor_sync(0xffffffffu, ps1, 2);
            if ((lane & 3) == 0) {
                int r = mb2 * 16 + (lane >> 2);
                sp[r * 2 + head2] = ps0 + b2v;
                sp[(r + 8) * 2 + head2] = ps1 + b2v;
            }
        }
        __syncthreads();

        // ---- stage3: out[h][c] += (stH+stL) * p ----
        {
            const __nv_bfloat16* sH = (const __nv_bfloat16*)(smc + OFF_STH);
            const __nv_bfloat16* sL = (const __nv_bfloat16*)(smc + OFF_STL);
            int c = tid & 127;
            int rhalf = tid >> 7;
            int h = c >> 6;
            float local = 0.f;
            int rb0 = rhalf * 32;
#pragma unroll 8
            for (int r = rb0; r < rb0 + 32; r++) {
                float sv = __bfloat162float(sH[r * STSTR + c])
                         + __bfloat162float(sL[r * STSTR + c]);
                local += sv * sp[r * 2 + h];
            }
            sacc[rhalf * 128 + c] += local;
        }
        __syncthreads();
    }

    if (tid < 128)
        out[(size_t)br * Bb * HD + (size_t)b * HD + tid] = sacc[tid] + sacc[128 + tid];
}

// ---------------------------------------------------------------------------
extern "C" void kernel_launch(void* const* d_in, const int* in_sizes, int n_in,
                              void* d_out, int out_size) {
    const float* lx   = (const float*)d_in[0];
    const float* nx   = (const float*)d_in[1];
    const float* y    = (const float*)d_in[2];
    const float* uid  = (const float*)d_in[3];
    const float* osb  = (const float*)d_in[4];
    const float* zipc = (const float*)d_in[5];
    const float* wty  = (const float*)d_in[6];
    const float* bty  = (const float*)d_in[7];
    const float* aty  = (const float*)d_in[8];
    const float* wlx  = (const float*)d_in[9];
    const float* blx  = (const float*)d_in[10];
    const float* alx  = (const float*)d_in[11];
    const float* wnx  = (const float*)d_in[12];
    const float* bnx  = (const float*)d_in[13];
    const float* anx  = (const float*)d_in[14];
    const float* lw1  = (const float*)d_in[15];
    const float* lb1  = (const float*)d_in[16];
    const float* la1  = (const float*)d_in[17];
    const float* lw2  = (const float*)d_in[18];
    const float* lb2  = (const float*)d_in[19];
    const float* nw1  = (const float*)d_in[20];
    const float* nb1  = (const float*)d_in[21];
    const float* na1  = (const float*)d_in[22];
    const float* nw2  = (const float*)d_in[23];
    const float* nb2  = (const float*)d_in[24];

    float* out = (float*)d_out;

    cudaFuncSetAttribute(main_kernel, cudaFuncAttributeMaxDynamicSharedMemorySize, SMEM_BYTES);

    dim3 g2(Bb, 2);
    prep_kernel<<<g2, 256>>>(y, wty, bty, aty, uid, osb, zipc,
                             lw1, lb1, nw1, nb1, wlx, wnx);
    main_kernel<<<g2, 256, SMEM_BYTES>>>(lx, nx, blx, alx, bnx, anx,
                                         la1, lb2, lw2, na1, nb2, nw2, out);
}

// round 15
// speedup vs baseline: 2.4458x; 1.0151x over previous
#include <cuda_runtime.h>
#include <cuda_bf16.h>
#include <math.h>
#include <stdint.h>

#define Bb 256
#define Ss 1024
#define Dd 64
#define HD 128
#define NJ 40
#define TILE 64
#define NTILES (Ss / TILE)

// bf16 row strides (elements)
#define XSTR 72      // x tiles: 144B rows
#define STSTR 136    // st: 272B rows
#define WSTR 136     // W: 272B rows
#define WESTR 104    // W_eff: 208B rows

typedef unsigned long long ull;

// ---------------- tensor-core helpers ----------------
__device__ __forceinline__ uint32_t smem_u32(const void* p) {
    uint32_t a;
    asm("{ .reg .u64 t; cvta.to.shared.u64 t, %1; cvt.u32.u64 %0, t; }" : "=r"(a) : "l"(p));
    return a;
}
__device__ __forceinline__ void ldsm4(uint32_t* r, uint32_t addr) {
    asm volatile("ldmatrix.sync.aligned.m8n8.x4.shared.b16 {%0,%1,%2,%3}, [%4];"
        : "=r"(r[0]), "=r"(r[1]), "=r"(r[2]), "=r"(r[3]) : "r"(addr));
}
__device__ __forceinline__ void ldsm4t(uint32_t* r, uint32_t addr) {
    asm volatile("ldmatrix.sync.aligned.m8n8.x4.trans.shared.b16 {%0,%1,%2,%3}, [%4];"
        : "=r"(r[0]), "=r"(r[1]), "=r"(r[2]), "=r"(r[3]) : "r"(addr));
}
__device__ __forceinline__ void mma_bf16(float* c, const uint32_t* a,
                                         uint32_t b0, uint32_t b1) {
    asm volatile("mma.sync.aligned.m16n8k16.row.col.f32.bf16.bf16.f32 "
        "{%0,%1,%2,%3}, {%4,%5,%6,%7}, {%8,%9}, {%0,%1,%2,%3};"
        : "+f"(c[0]), "+f"(c[1]), "+f"(c[2]), "+f"(c[3])
        : "r"(a[0]), "r"(a[1]), "r"(a[2]), "r"(a[3]), "r"(b0), "r"(b1));
}
#define GBAR(id) asm volatile("bar.sync %0, 128;" :: "r"(id) : "memory")

// ---------------- scratch ----------------
__device__ __nv_bfloat16 g_wh[2 * Dd * 128];
__device__ __nv_bfloat16 g_wl[2 * Dd * 128];
__device__ __nv_bfloat16 g_weH[2L * Bb * 64 * 96];
__device__ __nv_bfloat16 g_weL[2L * Bb * 64 * 96];
__device__ float g_cvec2[2L * Bb * 80];

// ---------------------------------------------------------------------------
// Prep (unchanged from R13)
// ---------------------------------------------------------------------------
__global__ void prep_kernel(const float* __restrict__ y,
                            const float* __restrict__ wty,
                            const float* __restrict__ bty,
                            const float* __restrict__ atyp,
                            const float* __restrict__ uid,
                            const float* __restrict__ osb,
                            const float* __restrict__ zipc,
                            const float* __restrict__ lw1,
                            const float* __restrict__ lb1,
                            const float* __restrict__ nw1,
                            const float* __restrict__ nb1,
                            const float* __restrict__ wlx,
                            const float* __restrict__ wnx) {
    __shared__ float sy[64];
    __shared__ float syt[128];
    __shared__ float sside[56];
    __shared__ float sred[4];
    int b = blockIdx.x;
    int br = blockIdx.y;
    int t = threadIdx.x;
    const float* w1 = br ? nw1 : lw1;
    const float* b1 = br ? nb1 : lb1;

    if (t < 64) sy[t] = y[b * 64 + t];
    if (t >= 64 && t < 96) sside[t - 64] = uid[b * 32 + (t - 64)];
    else if (t >= 96 && t < 104) sside[32 + (t - 96)] = osb[b * 8 + (t - 96)];
    else if (t >= 104 && t < 120) sside[40 + (t - 104)] = zipc[b * 16 + (t - 104)];
    __syncthreads();

    float vv = 0.f;
    if (t < 128) {
        float acc = bty[t];
#pragma unroll 8
        for (int d = 0; d < 64; d++) acc += sy[d] * wty[d * 128 + t];
        float a = *atyp;
        vv = (acc >= 0.f) ? acc : a * acc;
        float ss = vv * vv;
#pragma unroll
        for (int off = 16; off > 0; off >>= 1) ss += __shfl_xor_sync(0xffffffffu, ss, off);
        if ((t & 31) == 0) sred[t >> 5] = ss;
    }
    __syncthreads();
    if (t < 128) {
        float tot = sred[0] + sred[1] + sred[2] + sred[3];
        syt[t] = vv / fmaxf(sqrtf(tot), 1e-12f);
    }
    __syncthreads();

    size_t base = ((size_t)(br * Bb + b)) * (64 * 96);
    for (int i = t; i < 64 * 96; i += blockDim.x) {
        int d = i / 96;
        int col = i - d * 96;
        int h = col / 48;
        int jj = col - h * 48;
        float v = 0.f;
        if (jj < 40) {
            v = w1[d * NJ + jj] + w1[(128 + d) * NJ + jj]
              + syt[h * 64 + d] * w1[(64 + d) * NJ + jj];
        }
        __nv_bfloat16 hi = __float2bfloat16(v);
        g_weH[base + i] = hi;
        g_weL[base + i] = __float2bfloat16(v - __bfloat162float(hi));
    }
    if (t < 80) {
        int h = t / 40, j = t - h * 40;
        float acc = b1[j];
#pragma unroll 4
        for (int d = 0; d < 64; d++)
            acc += syt[h * 64 + d] * (w1[(192 + d) * NJ + j] - w1[(128 + d) * NJ + j]);
#pragma unroll 4
        for (int k2 = 0; k2 < 56; k2++)
            acc += sside[k2] * w1[(256 + k2) * NJ + j];
        g_cvec2[(size_t)(br * Bb + b) * 80 + t] = acc;
    }

    if (b == 0) {
        const float* wX = br ? wnx : wlx;
        for (int i = t; i < Dd * 128; i += blockDim.x) {
            float v = wX[i];
            __nv_bfloat16 hi = __float2bfloat16(v);
            __nv_bfloat16 lo = __float2bfloat16(v - __bfloat162float(hi));
            g_wh[br * Dd * 128 + i] = hi;
            g_wl[br * Dd * 128 + i] = lo;
        }
    }
}

// ---------------------------------------------------------------------------
// Main kernel: grid (256,2), block 256 = 2 independent 128-thread groups,
// each owning 32 rows of every 64-row tile. Named barriers per group.
// ---------------------------------------------------------------------------
// smem layout (bytes):
//  per-group region (17408 B each):
//    XH:+0 (32 x 144B)  / XL:+8704 (32 x 144B)    — unioned with:
//    STH:+0 (32 x 272B) / STL:+8704 (32 x 272B)
#define GRP_BYTES 17408
#define GRP_XLOFF 8704
#define OFF_G0   0
#define OFF_WH   34816      // 17408
#define OFF_WL   52224      // 17408
#define OFF_WEH  69632      // 13312
#define OFF_WEL  82944      // 13312
#define OFF_BX   96256      // 512
#define OFF_SRED 96768      // 2 x 256
#define OFF_SP   97280      // 2 x 256
#define OFF_SACC 97792      // 1024
#define OFF_CV   98816      // 320
#define OFF_W2   99136      // 160
#define SMEM_BYTES 99328

__global__ void __launch_bounds__(256, 2)
main_kernel(const float* __restrict__ lx,
            const float* __restrict__ nx,
            const float* __restrict__ blx, const float* __restrict__ alx,
            const float* __restrict__ bnx, const float* __restrict__ anx,
            const float* __restrict__ la1, const float* __restrict__ lb2,
            const float* __restrict__ lw2,
            const float* __restrict__ na1, const float* __restrict__ nb2,
            const float* __restrict__ nw2,
            float* __restrict__ out)
{
    extern __shared__ char smc[];
    float* sbx  = (float*)(smc + OFF_BX);
    float* sacc = (float*)(smc + OFF_SACC);
    float* scv  = (float*)(smc + OFF_CV);
    float* sw2  = (float*)(smc + OFF_W2);

    const int tid  = threadIdx.x;
    const int b    = blockIdx.x;
    const int br   = blockIdx.y;
    const int lane = tid & 31;
    const int wrp  = tid >> 5;
    const int grp  = wrp >> 2;           // 0 or 1
    const int wg   = wrp & 3;            // warp within group
    const int gtid = tid & 127;
    const int barid = grp + 1;

    const float* x  = br ? nx  : lx;
    const float* bX = br ? bnx : blx;
    const float aXv = br ? *anx : *alx;
    const float a1v = br ? *na1 : *la1;
    const float b2v = br ? *nb2 : *lb2;
    const float* w2 = br ? nw2 : lw2;

    const uint32_t sb = smem_u32(smc);
    const uint32_t gbase = sb + (uint32_t)(grp * GRP_BYTES);
    char* gmem = smc + grp * GRP_BYTES;
    float* sredg = (float*)(smc + OFF_SRED) + grp * 64;
    float* spg   = (float*)(smc + OFF_SP) + grp * 64;

    // ---- stage-in constants (full block) ----
    {
        const ull* gh = (const ull*)(g_wh + br * Dd * 128);
        const ull* gl = (const ull*)(g_wl + br * Dd * 128);
#pragma unroll
        for (int k = 0; k < 8; k++) {
            int q = tid + k * 256;
            int row = q >> 5;
            int c8 = (q & 31) * 8;
            *(ull*)(smc + OFF_WH + row * (WSTR * 2) + c8) = gh[q];
            *(ull*)(smc + OFF_WL + row * (WSTR * 2) + c8) = gl[q];
        }
        size_t base = ((size_t)(br * Bb + b)) * (64 * 96);
        const uint32_t* geh = (const uint32_t*)(g_weH + base);
        const uint32_t* gel = (const uint32_t*)(g_weL + base);
        uint32_t* weh = (uint32_t*)(smc + OFF_WEH);
        uint32_t* wel = (uint32_t*)(smc + OFF_WEL);
        for (int i = tid; i < 64 * 48; i += 256) {
            int d = i / 48, q = i - d * 48;
            weh[d * 52 + q] = geh[i];
            wel[d * 52 + q] = gel[i];
        }
        if (tid < 128) sbx[tid] = bX[tid];
        if (tid < 80)  scv[tid] = g_cvec2[(size_t)(br * Bb + b) * 80 + tid];
        if (tid < 40)  sw2[tid] = w2[tid];
        sacc[tid] = 0.f;
    }
    __syncthreads();

    // stage1 geometry (within group: 2 m-blocks x 2 n-halves over 32 rows)
    const int mbg = wg & 1;
    const int nhg = wg >> 1;
    const int lm = lane >> 3;
    const int lr = lane & 7;
    const uint32_t aoff = (uint32_t)((mbg * 16 + (lm & 1) * 8 + lr) * (XSTR * 2) + (lm >> 1) * 16);
    const uint32_t boff = (uint32_t)(((lm & 1) * 8 + lr) * (WSTR * 2) + (nhg * 64 + (lm >> 1) * 8) * 2);
    const int r0 = mbg * 16 + (lane >> 2);       // local rows r0, r0+8

    // stage2 geometry (within group: 2 heads x 2 m-blocks)
    const int head2 = wg >> 1;
    const int mb2 = wg & 1;
    const uint32_t a2off = (uint32_t)((mb2 * 16 + (lm & 1) * 8 + lr) * (STSTR * 2)
                                      + head2 * 128 + (lm >> 1) * 16);
    const uint32_t b2off = (uint32_t)(((lm & 1) * 8 + lr) * (WESTR * 2)
                                      + (head2 * 48 + (lm >> 1) * 8) * 2);
    float cb[5][2], w2l[5][2];
#pragma unroll
    for (int t5 = 0; t5 < 5; t5++) {
        int j0 = t5 * 8 + (lane & 3) * 2;
        cb[t5][0] = scv[head2 * 40 + j0];
        cb[t5][1] = scv[head2 * 40 + j0 + 1];
        w2l[t5][0] = sw2[j0];
        w2l[t5][1] = sw2[j0 + 1];
    }

    const float* xb = x + (size_t)b * Ss * Dd + (size_t)grp * 32 * Dd;

    for (int tile = 0; tile < NTILES; tile++) {
        // ---- convert group's 32 rows fp32 -> bf16 hi/lo ----
        {
            const float4* src = (const float4*)(xb + (size_t)tile * TILE * Dd);
#pragma unroll
            for (int k = 0; k < 4; k++) {
                int q = gtid + k * 128;          // 0..511 float4s = 32 rows
                float4 v = src[q];
                int row = q >> 4;
                int c8 = (q & 15) * 8;
                __nv_bfloat16 h0 = __float2bfloat16(v.x);
                __nv_bfloat16 h1 = __float2bfloat16(v.y);
                __nv_bfloat16 h2 = __float2bfloat16(v.z);
                __nv_bfloat16 h3 = __float2bfloat16(v.w);
                __nv_bfloat16 l0 = __float2bfloat16(v.x - __bfloat162float(h0));
                __nv_bfloat16 l1 = __float2bfloat16(v.y - __bfloat162float(h1));
                __nv_bfloat16 l2 = __float2bfloat16(v.z - __bfloat162float(h2));
                __nv_bfloat16 l3 = __float2bfloat16(v.w - __bfloat162float(h3));
                ull ph = (ull)__bfloat16_as_ushort(h0)
                       | ((ull)__bfloat16_as_ushort(h1) << 16)
                       | ((ull)__bfloat16_as_ushort(h2) << 32)
                       | ((ull)__bfloat16_as_ushort(h3) << 48);
                ull pl = (ull)__bfloat16_as_ushort(l0)
                       | ((ull)__bfloat16_as_ushort(l1) << 16)
                       | ((ull)__bfloat16_as_ushort(l2) << 32)
                       | ((ull)__bfloat16_as_ushort(l3) << 48);
                *(ull*)(gmem + row * (XSTR * 2) + c8) = ph;
                *(ull*)(gmem + GRP_XLOFF + row * (XSTR * 2) + c8) = pl;
            }
        }
        GBAR(barid);

        // ---- stage1 MMA: C = xhi@Whi + xlo@Whi + xhi@Wlo ----
        float C[8][4];
#pragma unroll
        for (int j = 0; j < 8; j++) { C[j][0] = C[j][1] = C[j][2] = C[j][3] = 0.f; }
#pragma unroll
        for (int ks = 0; ks < 4; ks++) {
            uint32_t ah[4], al[4];
            ldsm4(ah, gbase + aoff + ks * 32);
            ldsm4(al, gbase + GRP_XLOFF + aoff + ks * 32);
#pragma unroll
            for (int g = 0; g < 4; g++) {
                uint32_t bh[4], bl[4];
                uint32_t bstep = boff + (uint32_t)(ks * 16 * (WSTR * 2) + g * 32);
                ldsm4t(bh, sb + OFF_WH + bstep);
                ldsm4t(bl, sb + OFF_WL + bstep);
                mma_bf16(C[2 * g],     ah, bh[0], bh[1]);
                mma_bf16(C[2 * g],     al, bh[0], bh[1]);
                mma_bf16(C[2 * g],     ah, bl[0], bl[1]);
                mma_bf16(C[2 * g + 1], ah, bh[2], bh[3]);
                mma_bf16(C[2 * g + 1], al, bh[2], bh[3]);
                mma_bf16(C[2 * g + 1], ah, bl[2], bl[3]);
            }
        }

        // ---- epilogue: bias + prelu + partial ssq ----
        {
            float ssq0 = 0.f, ssq1 = 0.f;
#pragma unroll
            for (int j = 0; j < 8; j++) {
                int col = nhg * 64 + j * 8 + (lane & 3) * 2;
                float2 bb = *(const float2*)&sbx[col];
                float v0 = C[j][0] + bb.x; v0 = (v0 >= 0.f) ? v0 : aXv * v0;
                float v1 = C[j][1] + bb.y; v1 = (v1 >= 0.f) ? v1 : aXv * v1;
                float v2 = C[j][2] + bb.x; v2 = (v2 >= 0.f) ? v2 : aXv * v2;
                float v3 = C[j][3] + bb.y; v3 = (v3 >= 0.f) ? v3 : aXv * v3;
                C[j][0] = v0; C[j][1] = v1; C[j][2] = v2; C[j][3] = v3;
                ssq0 += v0 * v0 + v1 * v1;
                ssq1 += v2 * v2 + v3 * v3;
            }
            ssq0 += __shfl_xor_sync(0xffffffffu, ssq0, 1);
            ssq0 += __shfl_xor_sync(0xffffffffu, ssq0, 2);
            ssq1 += __shfl_xor_sync(0xffffffffu, ssq1, 1);
            ssq1 += __shfl_xor_sync(0xffffffffu, ssq1, 2);
            if ((lane & 3) == 0) {
                sredg[r0 * 2 + nhg] = ssq0;
                sredg[(r0 + 8) * 2 + nhg] = ssq1;
            }
        }
        GBAR(barid);   // ssq visible AND all XH/XL ldsm reads done

        // ---- normalize from regs -> st bf16 hi/lo (overwrites X union) ----
        {
            float rn0 = rsqrtf(fmaxf(sredg[r0 * 2] + sredg[r0 * 2 + 1], 1e-24f));
            float rn1 = rsqrtf(fmaxf(sredg[(r0 + 8) * 2] + sredg[(r0 + 8) * 2 + 1], 1e-24f));
#pragma unroll
            for (int j = 0; j < 8; j++) {
                int col = nhg * 64 + j * 8 + (lane & 3) * 2;
                float v0 = C[j][0] * rn0, v1 = C[j][1] * rn0;
                float v2 = C[j][2] * rn1, v3 = C[j][3] * rn1;
                __nv_bfloat16 h0 = __float2bfloat16(v0), h1 = __float2bfloat16(v1);
                __nv_bfloat16 h2 = __float2bfloat16(v2), h3 = __float2bfloat16(v3);
                uint32_t ph0 = (uint32_t)__bfloat16_as_ushort(h0)
                             | ((uint32_t)__bfloat16_as_ushort(h1) << 16);
                uint32_t pl0 = (uint32_t)__bfloat16_as_ushort(__float2bfloat16(v0 - __bfloat162float(h0)))
                             | ((uint32_t)__bfloat16_as_ushort(__float2bfloat16(v1 - __bfloat162float(h1))) << 16);
                uint32_t ph1 = (uint32_t)__bfloat16_as_ushort(h2)
                             | ((uint32_t)__bfloat16_as_ushort(h3) << 16);
                uint32_t pl1 = (uint32_t)__bfloat16_as_ushort(__float2bfloat16(v2 - __bfloat162float(h2)))
                             | ((uint32_t)__bfloat16_as_ushort(__float2bfloat16(v3 - __bfloat162float(h3))) << 16);
                *(uint32_t*)(gmem + r0 * (STSTR * 2) + col * 2) = ph0;
                *(uint32_t*)(gmem + GRP_XLOFF + r0 * (STSTR * 2) + col * 2) = pl0;
                *(uint32_t*)(gmem + (r0 + 8) * (STSTR * 2) + col * 2) = ph1;
                *(uint32_t*)(gmem + GRP_XLOFF + (r0 + 8) * (STSTR * 2) + col * 2) = pl1;
            }
        }
        GBAR(barid);

        // ---- stage2 MMA: C2 = st @ W_eff, p = prelu(.)·w2 ----
        {
            float C2[5][4];
#pragma unroll
            for (int t5 = 0; t5 < 5; t5++)
                C2[t5][0] = C2[t5][1] = C2[t5][2] = C2[t5][3] = 0.f;
#pragma unroll
            for (int ks = 0; ks < 4; ks++) {
                uint32_t ah[4], al[4];
                ldsm4(ah, gbase + a2off + ks * 32);
                ldsm4(al, gbase + GRP_XLOFF + a2off + ks * 32);
#pragma unroll
                for (int ch = 0; ch < 3; ch++) {
                    uint32_t bh[4], bl[4];
                    uint32_t bstep = b2off + (uint32_t)(ks * 16 * (WESTR * 2) + ch * 32);
                    ldsm4t(bh, sb + OFF_WEH + bstep);
                    ldsm4t(bl, sb + OFF_WEL + bstep);
                    mma_bf16(C2[2 * ch], ah, bh[0], bh[1]);
                    mma_bf16(C2[2 * ch], al, bh[0], bh[1]);
                    mma_bf16(C2[2 * ch], ah, bl[0], bl[1]);
                    if (ch < 2) {
                        mma_bf16(C2[2 * ch + 1], ah, bh[2], bh[3]);
                        mma_bf16(C2[2 * ch + 1], al, bh[2], bh[3]);
                        mma_bf16(C2[2 * ch + 1], ah, bl[2], bl[3]);
                    }
                }
            }
            float ps0 = 0.f, ps1 = 0.f;
#pragma unroll
            for (int t5 = 0; t5 < 5; t5++) {
                float v;
                v = C2[t5][0] + cb[t5][0]; v = (v >= 0.f) ? v : a1v * v; ps0 += v * w2l[t5][0];
                v = C2[t5][1] + cb[t5][1]; v = (v >= 0.f) ? v : a1v * v; ps0 += v * w2l[t5][1];
                v = C2[t5][2] + cb[t5][0]; v = (v >= 0.f) ? v : a1v * v; ps1 += v * w2l[t5][0];
                v = C2[t5][3] + cb[t5][1]; v = (v >= 0.f) ? v : a1v * v; ps1 += v * w2l[t5][1];
            }
            ps0 += __shfl_xor_sync(0xffffffffu, ps0, 1);
            ps0 += __shfl_xor_sync(0xffffffffu, ps0, 2);
            ps1 += __shfl_xor_sync(0xffffffffu, ps1, 1);
            ps1 += __shfl_xor_sync(0xffffffffu, ps1, 2);
            if ((lane & 3) == 0) {
                int r = mb2 * 16 + (lane >> 2);
                spg[r * 2 + head2] = ps0 + b2v;
                spg[(r + 8) * 2 + head2] = ps1 + b2v;
            }
        }
        GBAR(barid);

        // ---- stage3: sacc[grp][c] += (stH+stL) * p over group's 32 rows ----
        {
            const __nv_bfloat16* sH = (const __nv_bfloat16*)gmem;
            const __nv_bfloat16* sL = (const __nv_bfloat16*)(gmem + GRP_XLOFF);
            int c = wg * 32 + lane;
            int h = c >> 6;
            float local = 0.f;
#pragma unroll 8
            for (int r = 0; r < 32; r++) {
                float sv = __bfloat162float(sH[r * STSTR + c])
                         + __bfloat162float(sL[r * STSTR + c]);
                local += sv * spg[r * 2 + h];
            }
            sacc[grp * 128 + c] += local;
        }
        GBAR(barid);   // stage3 reads done before next tile's convert overwrites
    }

    __syncthreads();
    if (tid < 128)
        out[(size_t)br * Bb * HD + (size_t)b * HD + tid] = sacc[tid] + sacc[128 + tid];
}

// ---------------------------------------------------------------------------
extern "C" void kernel_launch(void* const* d_in, const int* in_sizes, int n_in,
                              void* d_out, int out_size) {
    const float* lx   = (const float*)d_in[0];
    const float* nx   = (const float*)d_in[1];
    const float* y    = (const float*)d_in[2];
    const float* uid  = (const float*)d_in[3];
    const float* osb  = (const float*)d_in[4];
    const float* zipc = (const float*)d_in[5];
    const float* wty  = (const float*)d_in[6];
    const float* bty  = (const float*)d_in[7];
    const float* aty  = (const float*)d_in[8];
    const float* wlx  = (const float*)d_in[9];
    const float* blx  = (const float*)d_in[10];
    const float* alx  = (const float*)d_in[11];
    const float* wnx  = (const float*)d_in[12];
    const float* bnx  = (const float*)d_in[13];
    const float* anx  = (const float*)d_in[14];
    const float* lw1  = (const float*)d_in[15];
    const float* lb1  = (const float*)d_in[16];
    const float* la1  = (const float*)d_in[17];
    const float* lw2  = (const float*)d_in[18];
    const float* lb2  = (const float*)d_in[19];
    const float* nw1  = (const float*)d_in[20];
    const float* nb1  = (const float*)d_in[21];
    const float* na1  = (const float*)d_in[22];
    const float* nw2  = (const float*)d_in[23];
    const float* nb2  = (const float*)d_in[24];

    float* out = (float*)d_out;

    cudaFuncSetAttribute(main_kernel, cudaFuncAttributeMaxDynamicSharedMemorySize, SMEM_BYTES);

    dim3 g2(Bb, 2);
    prep_kernel<<<g2, 256>>>(y, wty, bty, aty, uid, osb, zipc,
                             lw1, lb1, nw1, nb1, wlx, wnx);
    main_kernel<<<g2, 256, SMEM_BYTES>>>(lx, nx, blx, alx, bnx, anx,
                                         la1, lb2, lw2, na1, nb2, nw2, out);
}